// round 4
// baseline (speedup 1.0000x reference)
#include <cuda_runtime.h>
#include <cuda_bf16.h>
#include <math.h>

#define N_NODES 50000
#define F_IN    2048
#define POOLD   1024

// ---------------- scratch (static device globals; no allocations) -------------
__device__ float g_h  [(size_t)N_NODES * 1024];  // pooled+LN
__device__ float g_h0 [(size_t)N_NODES * 512];
__device__ float g_h1 [(size_t)N_NODES * 128];
__device__ float g_h2 [(size_t)N_NODES * 64];
__device__ float g_xw1[(size_t)N_NODES * 32];
__device__ float g_ac1[(size_t)N_NODES * 32];    // gcn1 accumulator / activated
__device__ float g_xw2[(size_t)N_NODES * 16];
__device__ float g_ac2[(size_t)N_NODES * 16];    // gcn2 accumulator (z before bias)
__device__ float g_dinv[N_NODES];                 // deg -> rsqrt(deg)

__device__ __forceinline__ float elu1(float v) { return v > 0.f ? v : expm1f(v); }

// ---------------- degree ------------------------------------------------------
__global__ void deg_init_kernel(float* deg) {
    int i = blockIdx.x * blockDim.x + threadIdx.x;
    if (i < N_NODES) deg[i] = 1.0f;  // self loop
}
__global__ void deg_accum_kernel(const int* __restrict__ dst, float* deg, int E) {
    int e = blockIdx.x * blockDim.x + threadIdx.x;
    if (e < E) atomicAdd(&deg[dst[e]], 1.0f);
}
__global__ void deg_final_kernel(float* deg) {
    int i = blockIdx.x * blockDim.x + threadIdx.x;
    if (i < N_NODES) deg[i] = rsqrtf(deg[i]);   // deg >= 1
}

// ---------------- maxpool(2) + layernorm --------------------------------------
__global__ void pool_ln_kernel(const float* __restrict__ x,
                               const float* __restrict__ g,
                               const float* __restrict__ b,
                               float* __restrict__ h) {
    int n = blockIdx.x;
    int t = threadIdx.x;  // 256
    const float2* xr = (const float2*)(x + (size_t)n * F_IN);
    float m[4];
    float sum = 0.f, sumsq = 0.f;
#pragma unroll
    for (int jj = 0; jj < 4; jj++) {
        int j = jj * 256 + t;
        float2 v = xr[j];
        float mm = fmaxf(v.x, v.y);
        m[jj] = mm;
        sum += mm;
        sumsq += mm * mm;
    }
    __shared__ float ssum[8], ssq[8];
#pragma unroll
    for (int off = 16; off > 0; off >>= 1) {
        sum   += __shfl_down_sync(0xffffffffu, sum, off);
        sumsq += __shfl_down_sync(0xffffffffu, sumsq, off);
    }
    int w = t >> 5, l = t & 31;
    if (l == 0) { ssum[w] = sum; ssq[w] = sumsq; }
    __syncthreads();
    __shared__ float s_mu, s_rstd;
    if (t == 0) {
        float S = 0.f, Q = 0.f;
#pragma unroll
        for (int i = 0; i < 8; i++) { S += ssum[i]; Q += ssq[i]; }
        float mu = S * (1.0f / POOLD);
        float var = Q * (1.0f / POOLD) - mu * mu;
        s_mu = mu;
        s_rstd = rsqrtf(var + 1e-5f);
    }
    __syncthreads();
    float mu = s_mu, rstd = s_rstd;
    float* hr = h + (size_t)n * POOLD;
#pragma unroll
    for (int jj = 0; jj < 4; jj++) {
        int j = jj * 256 + t;
        hr[j] = (m[jj] - mu) * rstd * g[j] + b[j];
    }
}

// ---------------- tiled SGEMM: C = act(A[MxK] @ B[KxN] + bias) -----------------
#define BM 128
#define BN 64
#define BK 16
#define TM 8
#define TN 4

__global__ __launch_bounds__(256) void sgemm_bias_act(
    const float* __restrict__ A, const float* __restrict__ B,
    const float* __restrict__ bias, float* __restrict__ C,
    int M, int N, int K, int do_elu) {
    __shared__ float As[BK][BM + 4];
    __shared__ float Bs[BK][BN];
    int tid = threadIdx.x;             // 256
    int tx = tid & 15, ty = tid >> 4;  // 16x16 thread grid
    int rowBase = blockIdx.x * BM;
    int colBase = blockIdx.y * BN;

    float acc[TM][TN];
#pragma unroll
    for (int i = 0; i < TM; i++)
#pragma unroll
        for (int j = 0; j < TN; j++) acc[i][j] = 0.f;

    int ar = tid >> 2;          // 0..63
    int ac = (tid & 3) * 4;     // 0,4,8,12
    int br = tid >> 4;          // 0..15
    int bc = (tid & 15) * 4;    // 0..60

    for (int k0 = 0; k0 < K; k0 += BK) {
#pragma unroll
        for (int gidx = 0; gidx < 2; gidx++) {
            int r = ar + gidx * 64;
            int grow = rowBase + r;
            float4 v = make_float4(0.f, 0.f, 0.f, 0.f);
            if (grow < M) v = *(const float4*)&A[(size_t)grow * K + k0 + ac];
            As[ac + 0][r] = v.x; As[ac + 1][r] = v.y;
            As[ac + 2][r] = v.z; As[ac + 3][r] = v.w;
        }
        {
            float4 v = *(const float4*)&B[(size_t)(k0 + br) * N + colBase + bc];
            Bs[br][bc + 0] = v.x; Bs[br][bc + 1] = v.y;
            Bs[br][bc + 2] = v.z; Bs[br][bc + 3] = v.w;
        }
        __syncthreads();
#pragma unroll
        for (int k = 0; k < BK; k++) {
            float ra[TM], rb[TN];
#pragma unroll
            for (int i = 0; i < TM; i++) ra[i] = As[k][ty * TM + i];
#pragma unroll
            for (int j = 0; j < TN; j++) rb[j] = Bs[k][tx * TN + j];
#pragma unroll
            for (int i = 0; i < TM; i++)
#pragma unroll
                for (int j = 0; j < TN; j++) acc[i][j] += ra[i] * rb[j];
        }
        __syncthreads();
    }
#pragma unroll
    for (int i = 0; i < TM; i++) {
        int grow = rowBase + ty * TM + i;
        if (grow >= M) continue;
#pragma unroll
        for (int j = 0; j < TN; j++) {
            int gcol = colBase + tx * TN + j;
            float v = acc[i][j] + bias[gcol];
            if (do_elu) v = elu1(v);
            C[(size_t)grow * N + gcol] = v;
        }
    }
}

// ---------------- GCN1: xw = h2 @ c1w (64->32), + self-loop init ----------------
__global__ __launch_bounds__(256) void gcn_xw1_kernel(
    const float* __restrict__ h2, const float* __restrict__ W,  // 64x32
    const float* __restrict__ dinv,
    float* __restrict__ xw, float* __restrict__ outbuf) {
    __shared__ float sW[64 * 32];
    int tid = threadIdx.x;
    for (int i = tid; i < 64 * 32; i += 256) sW[i] = W[i];
    __syncthreads();
    int warp = tid >> 5, lane = tid & 31;
    int n = blockIdx.x * 8 + warp;
    if (n >= N_NODES) return;
    const float* row = h2 + (size_t)n * 64;
    float r0 = row[lane], r1 = row[lane + 32];
    float accv = 0.f;
#pragma unroll
    for (int k = 0; k < 32; k++) {
        float a = __shfl_sync(0xffffffffu, r0, k);
        accv += a * sW[k * 32 + lane];
    }
#pragma unroll
    for (int k = 0; k < 32; k++) {
        float a = __shfl_sync(0xffffffffu, r1, k);
        accv += a * sW[(k + 32) * 32 + lane];
    }
    float di = dinv[n];
    xw[(size_t)n * 32 + lane] = accv;
    outbuf[(size_t)n * 32 + lane] = accv * di * di;
}

// scatter: out[dst] += xw[src]*dinv[src]*dinv[dst], 32 channels, thread per (e,c)
__global__ void gcn_scatter32_kernel(const int* __restrict__ src,
                                     const int* __restrict__ dst,
                                     const float* __restrict__ dinv,
                                     const float* __restrict__ xw,
                                     float* __restrict__ outbuf, int E) {
    int idx = blockIdx.x * blockDim.x + threadIdx.x;
    int e = idx >> 5, c = idx & 31;
    if (e >= E) return;
    int s = src[e], d = dst[e];
    float w = dinv[s] * dinv[d];
    atomicAdd(&outbuf[(size_t)d * 32 + c], xw[(size_t)s * 32 + c] * w);
}

__global__ void bias_elu32_kernel(float* __restrict__ buf,
                                  const float* __restrict__ bias, int total) {
    int i = blockIdx.x * blockDim.x + threadIdx.x;
    if (i < total) {
        float v = buf[i] + bias[i & 31];
        buf[i] = elu1(v);
    }
}

// ---------------- GCN2: xw2 = act1 @ c2w (32->16), + self-loop init -------------
__global__ __launch_bounds__(256) void gcn_xw2_kernel(
    const float* __restrict__ g1, const float* __restrict__ W,  // 32x16
    const float* __restrict__ dinv,
    float* __restrict__ xw, float* __restrict__ outbuf) {
    __shared__ float sW[32 * 16];
    int tid = threadIdx.x;
    for (int i = tid; i < 32 * 16; i += 256) sW[i] = W[i];
    __syncthreads();
    int warp = tid >> 5, lane = tid & 31;
    int n = blockIdx.x * 8 + warp;
    if (n >= N_NODES) return;
    float r = g1[(size_t)n * 32 + lane];
    float accv = 0.f;
#pragma unroll
    for (int k = 0; k < 32; k++) {
        float a = __shfl_sync(0xffffffffu, r, k);
        if (lane < 16) accv += a * sW[k * 16 + lane];
    }
    if (lane < 16) {
        float di = dinv[n];
        xw[(size_t)n * 16 + lane] = accv;
        outbuf[(size_t)n * 16 + lane] = accv * di * di;
    }
}

__global__ void gcn_scatter16_kernel(const int* __restrict__ src,
                                     const int* __restrict__ dst,
                                     const float* __restrict__ dinv,
                                     const float* __restrict__ xw,
                                     float* __restrict__ outbuf, int E) {
    int idx = blockIdx.x * blockDim.x + threadIdx.x;
    int e = idx >> 4, c = idx & 15;
    if (e >= E) return;
    int s = src[e], d = dst[e];
    float w = dinv[s] * dinv[d];
    atomicAdd(&outbuf[(size_t)d * 16 + c], xw[(size_t)s * 16 + c] * w);
}

// ---------------- edge head -----------------------------------------------------
__global__ __launch_bounds__(256) void edge_head_kernel(
    const int* __restrict__ ei, const int* __restrict__ mask,
    const float* __restrict__ z, const float* __restrict__ c2b,
    const float* __restrict__ lw1, const float* __restrict__ lb1,
    const float* __restrict__ lw2, const float* __restrict__ lb2,
    float* __restrict__ out, int nsel, int E) {
    __shared__ float sW1[32 * 16], sB1[16], sW2[16 * 2], sB2[2], sCB[16];
    int tid = threadIdx.x;
    for (int i = tid; i < 512; i += 256) sW1[i] = lw1[i];
    if (tid < 16) { sB1[tid] = lb1[tid]; sCB[tid] = c2b[tid]; }
    if (tid < 32) sW2[tid] = lw2[tid];
    if (tid < 2)  sB2[tid] = lb2[tid];
    __syncthreads();
    int j = blockIdx.x * 256 + tid;
    if (j >= nsel) return;
    int idx = mask[j];
    int s = ei[idx], d = ei[E + idx];
    float e[32];
#pragma unroll
    for (int k = 0; k < 16; k++) e[k]      = z[(size_t)s * 16 + k] + sCB[k];
#pragma unroll
    for (int k = 0; k < 16; k++) e[16 + k] = z[(size_t)d * 16 + k] + sCB[k];
    float a1[16];
#pragma unroll
    for (int q = 0; q < 16; q++) {
        float accv = sB1[q];
#pragma unroll
        for (int k = 0; k < 32; k++) accv += e[k] * sW1[k * 16 + q];
        a1[q] = elu1(accv);
    }
    float o0 = sB2[0], o1 = sB2[1];
#pragma unroll
    for (int q = 0; q < 16; q++) {
        o0 += a1[q] * sW2[q * 2 + 0];
        o1 += a1[q] * sW2[q * 2 + 1];
    }
    out[(size_t)j * 2 + 0] = o0;
    out[(size_t)j * 2 + 1] = o1;
}

// ---------------- launch --------------------------------------------------------
extern "C" void kernel_launch(void* const* d_in, const int* in_sizes, int n_in,
                              void* d_out, int out_size) {
    const float* x    = (const float*)d_in[0];
    const int*   ei   = (const int*)d_in[1];
    const int*   mask = (const int*)d_in[2];
    const float* ln_g = (const float*)d_in[3];
    const float* ln_b = (const float*)d_in[4];
    const float* w0   = (const float*)d_in[5];
    const float* b0   = (const float*)d_in[6];
    const float* w1   = (const float*)d_in[7];
    const float* b1   = (const float*)d_in[8];
    const float* w2   = (const float*)d_in[9];
    const float* b2   = (const float*)d_in[10];
    const float* c1w  = (const float*)d_in[11];
    const float* c1b  = (const float*)d_in[12];
    const float* c2w  = (const float*)d_in[13];
    const float* c2b  = (const float*)d_in[14];
    const float* lw1  = (const float*)d_in[15];
    const float* lb1  = (const float*)d_in[16];
    const float* lw2  = (const float*)d_in[17];
    const float* lb2  = (const float*)d_in[18];

    int E    = in_sizes[1] / 2;
    int nsel = in_sizes[2];

    float *h, *h0, *h1, *h2, *xw1, *ac1, *xw2, *ac2, *dinv;
    cudaGetSymbolAddress((void**)&h,   g_h);
    cudaGetSymbolAddress((void**)&h0,  g_h0);
    cudaGetSymbolAddress((void**)&h1,  g_h1);
    cudaGetSymbolAddress((void**)&h2,  g_h2);
    cudaGetSymbolAddress((void**)&xw1, g_xw1);
    cudaGetSymbolAddress((void**)&ac1, g_ac1);
    cudaGetSymbolAddress((void**)&xw2, g_xw2);
    cudaGetSymbolAddress((void**)&ac2, g_ac2);
    cudaGetSymbolAddress((void**)&dinv, g_dinv);

    const int T = 256;
    // degrees
    deg_init_kernel<<<(N_NODES + T - 1) / T, T>>>(dinv);
    deg_accum_kernel<<<(E + T - 1) / T, T>>>(ei + E, dinv, E);
    deg_final_kernel<<<(N_NODES + T - 1) / T, T>>>(dinv);

    // maxpool + layernorm
    pool_ln_kernel<<<N_NODES, 256>>>(x, ln_g, ln_b, h);

    // MLP stack
    {
        dim3 grid((N_NODES + BM - 1) / BM, 512 / BN);
        sgemm_bias_act<<<grid, 256>>>(h, w0, b0, h0, N_NODES, 512, 1024, 1);
    }
    {
        dim3 grid((N_NODES + BM - 1) / BM, 128 / BN);
        sgemm_bias_act<<<grid, 256>>>(h0, w1, b1, h1, N_NODES, 128, 512, 1);
    }
    {
        dim3 grid((N_NODES + BM - 1) / BM, 64 / BN);
        sgemm_bias_act<<<grid, 256>>>(h1, w2, b2, h2, N_NODES, 64, 128, 1);
    }

    // GCN conv 1 (64->32)
    gcn_xw1_kernel<<<(N_NODES + 7) / 8, 256>>>(h2, c1w, dinv, xw1, ac1);
    {
        long long tot = (long long)E * 32;
        gcn_scatter32_kernel<<<(int)((tot + T - 1) / T), T>>>(ei, ei + E, dinv, xw1, ac1, E);
    }
    bias_elu32_kernel<<<(N_NODES * 32 + T - 1) / T, T>>>(ac1, c1b, N_NODES * 32);

    // GCN conv 2 (32->16)
    gcn_xw2_kernel<<<(N_NODES + 7) / 8, 256>>>(ac1, c2w, dinv, xw2, ac2);
    {
        long long tot = (long long)E * 16;
        gcn_scatter16_kernel<<<(int)((tot + T - 1) / T), T>>>(ei, ei + E, dinv, xw2, ac2, E);
    }

    // edge head
    edge_head_kernel<<<(nsel + 255) / 256, 256>>>(ei, mask, ac2, c2b, lw1, lb1, lw2,
                                                  lb2, (float*)d_out, nsel, E);
}

// round 5
// speedup vs baseline: 1.4174x; 1.4174x over previous
#include <cuda_runtime.h>
#include <cuda_bf16.h>
#include <math.h>

#define N_NODES 50000
#define F_IN    2048
#define POOLD   1024

// ---------------- scratch (static device globals; no allocations) -------------
__device__ float g_h  [(size_t)N_NODES * 1024];  // pooled+LN
__device__ float g_h0 [(size_t)N_NODES * 512];
__device__ float g_h1 [(size_t)N_NODES * 128];
__device__ float g_h2 [(size_t)N_NODES * 64];
__device__ float g_xw1[(size_t)N_NODES * 32];
__device__ float g_ac1[(size_t)N_NODES * 32];    // gcn1 accumulator / activated
__device__ float g_xw2[(size_t)N_NODES * 16];
__device__ float g_ac2[(size_t)N_NODES * 16];    // gcn2 accumulator (z before bias)
__device__ float g_dinv[N_NODES];                 // deg -> rsqrt(deg)

__device__ __forceinline__ float elu1(float v) { return v > 0.f ? v : expm1f(v); }

__device__ __forceinline__ unsigned f2tf32(float v) {
    unsigned r;
    asm("cvt.rna.tf32.f32 %0, %1;" : "=r"(r) : "f"(v));
    return r;
}

// ---------------- degree ------------------------------------------------------
__global__ void deg_init_kernel(float* deg) {
    int i = blockIdx.x * blockDim.x + threadIdx.x;
    if (i < N_NODES) deg[i] = 1.0f;  // self loop
}
__global__ void deg_accum_kernel(const int* __restrict__ dst, float* deg, int E) {
    int e = blockIdx.x * blockDim.x + threadIdx.x;
    if (e < E) atomicAdd(&deg[dst[e]], 1.0f);
}
__global__ void deg_final_kernel(float* deg) {
    int i = blockIdx.x * blockDim.x + threadIdx.x;
    if (i < N_NODES) deg[i] = rsqrtf(deg[i]);   // deg >= 1
}

// ---------------- maxpool(2) + layernorm --------------------------------------
__global__ void pool_ln_kernel(const float* __restrict__ x,
                               const float* __restrict__ g,
                               const float* __restrict__ b,
                               float* __restrict__ h) {
    int n = blockIdx.x;
    int t = threadIdx.x;  // 256
    const float2* xr = (const float2*)(x + (size_t)n * F_IN);
    float m[4];
    float sum = 0.f, sumsq = 0.f;
#pragma unroll
    for (int jj = 0; jj < 4; jj++) {
        int j = jj * 256 + t;
        float2 v = xr[j];
        float mm = fmaxf(v.x, v.y);
        m[jj] = mm;
        sum += mm;
        sumsq += mm * mm;
    }
    __shared__ float ssum[8], ssq[8];
#pragma unroll
    for (int off = 16; off > 0; off >>= 1) {
        sum   += __shfl_down_sync(0xffffffffu, sum, off);
        sumsq += __shfl_down_sync(0xffffffffu, sumsq, off);
    }
    int w = t >> 5, l = t & 31;
    if (l == 0) { ssum[w] = sum; ssq[w] = sumsq; }
    __syncthreads();
    __shared__ float s_mu, s_rstd;
    if (t == 0) {
        float S = 0.f, Q = 0.f;
#pragma unroll
        for (int i = 0; i < 8; i++) { S += ssum[i]; Q += ssq[i]; }
        float mu = S * (1.0f / POOLD);
        float var = Q * (1.0f / POOLD) - mu * mu;
        s_mu = mu;
        s_rstd = rsqrtf(var + 1e-5f);
    }
    __syncthreads();
    float mu = s_mu, rstd = s_rstd;
    float* hr = h + (size_t)n * POOLD;
#pragma unroll
    for (int jj = 0; jj < 4; jj++) {
        int j = jj * 256 + t;
        hr[j] = (m[jj] - mu) * rstd * g[j] + b[j];
    }
}

// ---------------- tf32 tensor-core GEMM: C = act(A @ B + bias) -----------------
// A: [M,K] row-major fp32 (converted to tf32 on smem store)
// B: [K,N] row-major fp32 (converted to tf32 on smem store)
// Block tile 128x64x32, 256 threads = 8 warps in 4(M) x 2(N), warp tile 32x32.
// Requires: N % 64 == 0, K % 32 == 0 (true for our shapes).
#define GBM 128
#define GBN 64
#define GBK 32

__global__ __launch_bounds__(256) void tf32_gemm_bias_act(
    const float* __restrict__ A, const float* __restrict__ B,
    const float* __restrict__ bias, float* __restrict__ C,
    int M, int N, int K, int do_elu) {
    __shared__ unsigned As[GBK][GBM + 4];   // [k][m]
    __shared__ unsigned Bs[GBK][GBN + 4];   // [k][n]

    int tid = threadIdx.x;
    int warp = tid >> 5, lane = tid & 31;
    int lg = lane >> 2;   // group id 0..7
    int lq = lane & 3;    // thread-in-group 0..3
    int warpM = warp & 3, warpN = warp >> 2;
    int rowBase = blockIdx.x * GBM;
    int colBase = blockIdx.y * GBN;
    int Rw = warpM * 32;
    int Cw = warpN * 32;

    float acc[2][4][4];
#pragma unroll
    for (int mt = 0; mt < 2; mt++)
#pragma unroll
        for (int nt = 0; nt < 4; nt++)
#pragma unroll
            for (int r = 0; r < 4; r++) acc[mt][nt][r] = 0.f;

    for (int k0 = 0; k0 < K; k0 += GBK) {
        // ---- stage A tile: 128 rows x 32 k = 1024 float4, 4 per thread ----
#pragma unroll
        for (int i = 0; i < 4; i++) {
            int idx = i * 256 + tid;       // [0,1024)
            int row = idx >> 3;            // 0..127
            int kq  = (idx & 7) * 4;       // 0..28
            int grow = rowBase + row;
            float4 v = make_float4(0.f, 0.f, 0.f, 0.f);
            if (grow < M) v = *(const float4*)&A[(size_t)grow * K + k0 + kq];
            As[kq + 0][row] = f2tf32(v.x);
            As[kq + 1][row] = f2tf32(v.y);
            As[kq + 2][row] = f2tf32(v.z);
            As[kq + 3][row] = f2tf32(v.w);
        }
        // ---- stage B tile: 32 k x 64 n = 512 float4, 2 per thread ----
#pragma unroll
        for (int i = 0; i < 2; i++) {
            int idx = i * 256 + tid;       // [0,512)
            int row = idx >> 4;            // k row 0..31
            int nq  = (idx & 15) * 4;      // 0..60
            float4 v = *(const float4*)&B[(size_t)(k0 + row) * N + colBase + nq];
            Bs[row][nq + 0] = f2tf32(v.x);
            Bs[row][nq + 1] = f2tf32(v.y);
            Bs[row][nq + 2] = f2tf32(v.z);
            Bs[row][nq + 3] = f2tf32(v.w);
        }
        __syncthreads();

#pragma unroll
        for (int kk = 0; kk < GBK; kk += 8) {
            unsigned a[2][4], bfr[4][2];
#pragma unroll
            for (int mt = 0; mt < 2; mt++) {
                int r0 = Rw + mt * 16 + lg;
                a[mt][0] = As[kk + lq    ][r0];
                a[mt][1] = As[kk + lq    ][r0 + 8];
                a[mt][2] = As[kk + lq + 4][r0];
                a[mt][3] = As[kk + lq + 4][r0 + 8];
            }
#pragma unroll
            for (int nt = 0; nt < 4; nt++) {
                int c0 = Cw + nt * 8 + lg;
                bfr[nt][0] = Bs[kk + lq    ][c0];
                bfr[nt][1] = Bs[kk + lq + 4][c0];
            }
#pragma unroll
            for (int mt = 0; mt < 2; mt++)
#pragma unroll
                for (int nt = 0; nt < 4; nt++) {
                    asm volatile(
                        "mma.sync.aligned.m16n8k8.row.col.f32.tf32.tf32.f32 "
                        "{%0,%1,%2,%3}, {%4,%5,%6,%7}, {%8,%9}, {%0,%1,%2,%3};"
                        : "+f"(acc[mt][nt][0]), "+f"(acc[mt][nt][1]),
                          "+f"(acc[mt][nt][2]), "+f"(acc[mt][nt][3])
                        : "r"(a[mt][0]), "r"(a[mt][1]), "r"(a[mt][2]), "r"(a[mt][3]),
                          "r"(bfr[nt][0]), "r"(bfr[nt][1]));
                }
        }
        __syncthreads();
    }

    // ---- epilogue: bias + optional ELU ----
#pragma unroll
    for (int mt = 0; mt < 2; mt++) {
#pragma unroll
        for (int nt = 0; nt < 4; nt++) {
            int col = colBase + Cw + nt * 8 + lq * 2;
            float b0 = bias[col], b1 = bias[col + 1];
            int r0 = rowBase + Rw + mt * 16 + lg;
            if (r0 < M) {
                float v0 = acc[mt][nt][0] + b0;
                float v1 = acc[mt][nt][1] + b1;
                if (do_elu) { v0 = elu1(v0); v1 = elu1(v1); }
                C[(size_t)r0 * N + col] = v0;
                C[(size_t)r0 * N + col + 1] = v1;
            }
            int r1 = r0 + 8;
            if (r1 < M) {
                float v2 = acc[mt][nt][2] + b0;
                float v3 = acc[mt][nt][3] + b1;
                if (do_elu) { v2 = elu1(v2); v3 = elu1(v3); }
                C[(size_t)r1 * N + col] = v2;
                C[(size_t)r1 * N + col + 1] = v3;
            }
        }
    }
}

// ---------------- tiled fp32 SGEMM (kept for the small 128->64 layer) ----------
#define BM 128
#define BN 64
#define BK 16
#define TM 8
#define TN 4

__global__ __launch_bounds__(256) void sgemm_bias_act(
    const float* __restrict__ A, const float* __restrict__ B,
    const float* __restrict__ bias, float* __restrict__ C,
    int M, int N, int K, int do_elu) {
    __shared__ float As[BK][BM + 4];
    __shared__ float Bs[BK][BN];
    int tid = threadIdx.x;
    int tx = tid & 15, ty = tid >> 4;
    int rowBase = blockIdx.x * BM;
    int colBase = blockIdx.y * BN;

    float acc[TM][TN];
#pragma unroll
    for (int i = 0; i < TM; i++)
#pragma unroll
        for (int j = 0; j < TN; j++) acc[i][j] = 0.f;

    int ar = tid >> 2;
    int ac = (tid & 3) * 4;
    int br = tid >> 4;
    int bc = (tid & 15) * 4;

    for (int k0 = 0; k0 < K; k0 += BK) {
#pragma unroll
        for (int gidx = 0; gidx < 2; gidx++) {
            int r = ar + gidx * 64;
            int grow = rowBase + r;
            float4 v = make_float4(0.f, 0.f, 0.f, 0.f);
            if (grow < M) v = *(const float4*)&A[(size_t)grow * K + k0 + ac];
            As[ac + 0][r] = v.x; As[ac + 1][r] = v.y;
            As[ac + 2][r] = v.z; As[ac + 3][r] = v.w;
        }
        {
            float4 v = *(const float4*)&B[(size_t)(k0 + br) * N + colBase + bc];
            Bs[br][bc + 0] = v.x; Bs[br][bc + 1] = v.y;
            Bs[br][bc + 2] = v.z; Bs[br][bc + 3] = v.w;
        }
        __syncthreads();
#pragma unroll
        for (int k = 0; k < BK; k++) {
            float ra[TM], rb[TN];
#pragma unroll
            for (int i = 0; i < TM; i++) ra[i] = As[k][ty * TM + i];
#pragma unroll
            for (int j = 0; j < TN; j++) rb[j] = Bs[k][tx * TN + j];
#pragma unroll
            for (int i = 0; i < TM; i++)
#pragma unroll
                for (int j = 0; j < TN; j++) acc[i][j] += ra[i] * rb[j];
        }
        __syncthreads();
    }
#pragma unroll
    for (int i = 0; i < TM; i++) {
        int grow = rowBase + ty * TM + i;
        if (grow >= M) continue;
#pragma unroll
        for (int j = 0; j < TN; j++) {
            int gcol = colBase + tx * TN + j;
            float v = acc[i][j] + bias[gcol];
            if (do_elu) v = elu1(v);
            C[(size_t)grow * N + gcol] = v;
        }
    }
}

// ---------------- GCN1: xw = h2 @ c1w (64->32), + self-loop init ----------------
__global__ __launch_bounds__(256) void gcn_xw1_kernel(
    const float* __restrict__ h2, const float* __restrict__ W,  // 64x32
    const float* __restrict__ dinv,
    float* __restrict__ xw, float* __restrict__ outbuf) {
    __shared__ float sW[64 * 32];
    int tid = threadIdx.x;
    for (int i = tid; i < 64 * 32; i += 256) sW[i] = W[i];
    __syncthreads();
    int warp = tid >> 5, lane = tid & 31;
    int n = blockIdx.x * 8 + warp;
    if (n >= N_NODES) return;
    const float* row = h2 + (size_t)n * 64;
    float r0 = row[lane], r1 = row[lane + 32];
    float accv = 0.f;
#pragma unroll
    for (int k = 0; k < 32; k++) {
        float a = __shfl_sync(0xffffffffu, r0, k);
        accv += a * sW[k * 32 + lane];
    }
#pragma unroll
    for (int k = 0; k < 32; k++) {
        float a = __shfl_sync(0xffffffffu, r1, k);
        accv += a * sW[(k + 32) * 32 + lane];
    }
    float di = dinv[n];
    xw[(size_t)n * 32 + lane] = accv;
    outbuf[(size_t)n * 32 + lane] = accv * di * di;
}

// scatter: out[dst] += xw[src]*dinv[src]*dinv[dst], 32 channels, thread per (e,c)
__global__ void gcn_scatter32_kernel(const int* __restrict__ src,
                                     const int* __restrict__ dst,
                                     const float* __restrict__ dinv,
                                     const float* __restrict__ xw,
                                     float* __restrict__ outbuf, int E) {
    int idx = blockIdx.x * blockDim.x + threadIdx.x;
    int e = idx >> 5, c = idx & 31;
    if (e >= E) return;
    int s = src[e], d = dst[e];
    float w = dinv[s] * dinv[d];
    atomicAdd(&outbuf[(size_t)d * 32 + c], xw[(size_t)s * 32 + c] * w);
}

__global__ void bias_elu32_kernel(float* __restrict__ buf,
                                  const float* __restrict__ bias, int total) {
    int i = blockIdx.x * blockDim.x + threadIdx.x;
    if (i < total) {
        float v = buf[i] + bias[i & 31];
        buf[i] = elu1(v);
    }
}

// ---------------- GCN2: xw2 = act1 @ c2w (32->16), + self-loop init -------------
__global__ __launch_bounds__(256) void gcn_xw2_kernel(
    const float* __restrict__ g1, const float* __restrict__ W,  // 32x16
    const float* __restrict__ dinv,
    float* __restrict__ xw, float* __restrict__ outbuf) {
    __shared__ float sW[32 * 16];
    int tid = threadIdx.x;
    for (int i = tid; i < 32 * 16; i += 256) sW[i] = W[i];
    __syncthreads();
    int warp = tid >> 5, lane = tid & 31;
    int n = blockIdx.x * 8 + warp;
    if (n >= N_NODES) return;
    float r = g1[(size_t)n * 32 + lane];
    float accv = 0.f;
#pragma unroll
    for (int k = 0; k < 32; k++) {
        float a = __shfl_sync(0xffffffffu, r, k);
        if (lane < 16) accv += a * sW[k * 16 + lane];
    }
    if (lane < 16) {
        float di = dinv[n];
        xw[(size_t)n * 16 + lane] = accv;
        outbuf[(size_t)n * 16 + lane] = accv * di * di;
    }
}

__global__ void gcn_scatter16_kernel(const int* __restrict__ src,
                                     const int* __restrict__ dst,
                                     const float* __restrict__ dinv,
                                     const float* __restrict__ xw,
                                     float* __restrict__ outbuf, int E) {
    int idx = blockIdx.x * blockDim.x + threadIdx.x;
    int e = idx >> 4, c = idx & 15;
    if (e >= E) return;
    int s = src[e], d = dst[e];
    float w = dinv[s] * dinv[d];
    atomicAdd(&outbuf[(size_t)d * 16 + c], xw[(size_t)s * 16 + c] * w);
}

// ---------------- edge head -----------------------------------------------------
__global__ __launch_bounds__(256) void edge_head_kernel(
    const int* __restrict__ ei, const int* __restrict__ mask,
    const float* __restrict__ z, const float* __restrict__ c2b,
    const float* __restrict__ lw1, const float* __restrict__ lb1,
    const float* __restrict__ lw2, const float* __restrict__ lb2,
    float* __restrict__ out, int nsel, int E) {
    __shared__ float sW1[32 * 16], sB1[16], sW2[16 * 2], sB2[2], sCB[16];
    int tid = threadIdx.x;
    for (int i = tid; i < 512; i += 256) sW1[i] = lw1[i];
    if (tid < 16) { sB1[tid] = lb1[tid]; sCB[tid] = c2b[tid]; }
    if (tid < 32) sW2[tid] = lw2[tid];
    if (tid < 2)  sB2[tid] = lb2[tid];
    __syncthreads();
    int j = blockIdx.x * 256 + tid;
    if (j >= nsel) return;
    int idx = mask[j];
    int s = ei[idx], d = ei[E + idx];
    float e[32];
#pragma unroll
    for (int k = 0; k < 16; k++) e[k]      = z[(size_t)s * 16 + k] + sCB[k];
#pragma unroll
    for (int k = 0; k < 16; k++) e[16 + k] = z[(size_t)d * 16 + k] + sCB[k];
    float a1[16];
#pragma unroll
    for (int q = 0; q < 16; q++) {
        float accv = sB1[q];
#pragma unroll
        for (int k = 0; k < 32; k++) accv += e[k] * sW1[k * 16 + q];
        a1[q] = elu1(accv);
    }
    float o0 = sB2[0], o1 = sB2[1];
#pragma unroll
    for (int q = 0; q < 16; q++) {
        o0 += a1[q] * sW2[q * 2 + 0];
        o1 += a1[q] * sW2[q * 2 + 1];
    }
    out[(size_t)j * 2 + 0] = o0;
    out[(size_t)j * 2 + 1] = o1;
}

// ---------------- launch --------------------------------------------------------
extern "C" void kernel_launch(void* const* d_in, const int* in_sizes, int n_in,
                              void* d_out, int out_size) {
    const float* x    = (const float*)d_in[0];
    const int*   ei   = (const int*)d_in[1];
    const int*   mask = (const int*)d_in[2];
    const float* ln_g = (const float*)d_in[3];
    const float* ln_b = (const float*)d_in[4];
    const float* w0   = (const float*)d_in[5];
    const float* b0   = (const float*)d_in[6];
    const float* w1   = (const float*)d_in[7];
    const float* b1   = (const float*)d_in[8];
    const float* w2   = (const float*)d_in[9];
    const float* b2   = (const float*)d_in[10];
    const float* c1w  = (const float*)d_in[11];
    const float* c1b  = (const float*)d_in[12];
    const float* c2w  = (const float*)d_in[13];
    const float* c2b  = (const float*)d_in[14];
    const float* lw1  = (const float*)d_in[15];
    const float* lb1  = (const float*)d_in[16];
    const float* lw2  = (const float*)d_in[17];
    const float* lb2  = (const float*)d_in[18];

    int E    = in_sizes[1] / 2;
    int nsel = in_sizes[2];

    float *h, *h0, *h1, *h2, *xw1, *ac1, *xw2, *ac2, *dinv;
    cudaGetSymbolAddress((void**)&h,   g_h);
    cudaGetSymbolAddress((void**)&h0,  g_h0);
    cudaGetSymbolAddress((void**)&h1,  g_h1);
    cudaGetSymbolAddress((void**)&h2,  g_h2);
    cudaGetSymbolAddress((void**)&xw1, g_xw1);
    cudaGetSymbolAddress((void**)&ac1, g_ac1);
    cudaGetSymbolAddress((void**)&xw2, g_xw2);
    cudaGetSymbolAddress((void**)&ac2, g_ac2);
    cudaGetSymbolAddress((void**)&dinv, g_dinv);

    const int T = 256;
    // degrees
    deg_init_kernel<<<(N_NODES + T - 1) / T, T>>>(dinv);
    deg_accum_kernel<<<(E + T - 1) / T, T>>>(ei + E, dinv, E);
    deg_final_kernel<<<(N_NODES + T - 1) / T, T>>>(dinv);

    // maxpool + layernorm
    pool_ln_kernel<<<N_NODES, 256>>>(x, ln_g, ln_b, h);

    // MLP stack: big two layers on tensor cores (tf32), small one on fp32
    {
        dim3 grid((N_NODES + GBM - 1) / GBM, 512 / GBN);
        tf32_gemm_bias_act<<<grid, 256>>>(h, w0, b0, h0, N_NODES, 512, 1024, 1);
    }
    {
        dim3 grid((N_NODES + GBM - 1) / GBM, 128 / GBN);
        tf32_gemm_bias_act<<<grid, 256>>>(h0, w1, b1, h1, N_NODES, 128, 512, 1);
    }
    {
        dim3 grid((N_NODES + BM - 1) / BM, 64 / BN);
        sgemm_bias_act<<<grid, 256>>>(h1, w2, b2, h2, N_NODES, 64, 128, 1);
    }

    // GCN conv 1 (64->32)
    gcn_xw1_kernel<<<(N_NODES + 7) / 8, 256>>>(h2, c1w, dinv, xw1, ac1);
    {
        long long tot = (long long)E * 32;
        gcn_scatter32_kernel<<<(int)((tot + T - 1) / T), T>>>(ei, ei + E, dinv, xw1, ac1, E);
    }
    bias_elu32_kernel<<<(N_NODES * 32 + T - 1) / T, T>>>(ac1, c1b, N_NODES * 32);

    // GCN conv 2 (32->16)
    gcn_xw2_kernel<<<(N_NODES + 7) / 8, 256>>>(ac1, c2w, dinv, xw2, ac2);
    {
        long long tot = (long long)E * 16;
        gcn_scatter16_kernel<<<(int)((tot + T - 1) / T), T>>>(ei, ei + E, dinv, xw2, ac2, E);
    }

    // edge head
    edge_head_kernel<<<(nsel + 255) / 256, 256>>>(ei, mask, ac2, c2b, lw1, lb1, lw2,
                                                  lb2, (float*)d_out, nsel, E);
}

// round 6
// speedup vs baseline: 2.4328x; 1.7164x over previous
#include <cuda_runtime.h>
#include <cuda_bf16.h>
#include <math.h>
#include <stdint.h>

#define N_NODES 50000
#define F_IN    2048
#define POOLD   1024

// ---------------- scratch (static device globals; no allocations) -------------
__device__ float g_h  [(size_t)N_NODES * 1024];  // pooled+LN
__device__ float g_h0 [(size_t)N_NODES * 512];
__device__ float g_h1 [(size_t)N_NODES * 128];
__device__ float g_h2 [(size_t)N_NODES * 64];
__device__ float g_xw1[(size_t)N_NODES * 32];
__device__ float g_ac1[(size_t)N_NODES * 32];    // gcn1 accumulator / activated
__device__ float g_xw2[(size_t)N_NODES * 16];
__device__ float g_ac2[(size_t)N_NODES * 16];    // gcn2 accumulator (z before bias)
__device__ float g_dinv[N_NODES];                 // deg -> rsqrt(deg)

__device__ __forceinline__ float elu1(float v) { return v > 0.f ? v : expm1f(v); }

__device__ __forceinline__ unsigned f2tf32(float v) {
    unsigned r;
    asm("cvt.rna.tf32.f32 %0, %1;" : "=r"(r) : "f"(v));
    return r;
}

// ---------------- degree ------------------------------------------------------
__global__ void deg_init_kernel(float* deg) {
    int i = blockIdx.x * blockDim.x + threadIdx.x;
    if (i < N_NODES) deg[i] = 1.0f;  // self loop
}
__global__ void deg_accum_kernel(const int* __restrict__ dst, float* deg, int E) {
    int e = blockIdx.x * blockDim.x + threadIdx.x;
    if (e < E) atomicAdd(&deg[dst[e]], 1.0f);
}
__global__ void deg_final_kernel(float* deg) {
    int i = blockIdx.x * blockDim.x + threadIdx.x;
    if (i < N_NODES) deg[i] = rsqrtf(deg[i]);   // deg >= 1
}

// ---------------- maxpool(2) + layernorm --------------------------------------
__global__ void pool_ln_kernel(const float* __restrict__ x,
                               const float* __restrict__ g,
                               const float* __restrict__ b,
                               float* __restrict__ h) {
    int n = blockIdx.x;
    int t = threadIdx.x;  // 256
    const float2* xr = (const float2*)(x + (size_t)n * F_IN);
    float m[4];
    float sum = 0.f, sumsq = 0.f;
#pragma unroll
    for (int jj = 0; jj < 4; jj++) {
        int j = jj * 256 + t;
        float2 v = xr[j];
        float mm = fmaxf(v.x, v.y);
        m[jj] = mm;
        sum += mm;
        sumsq += mm * mm;
    }
    __shared__ float ssum[8], ssq[8];
#pragma unroll
    for (int off = 16; off > 0; off >>= 1) {
        sum   += __shfl_down_sync(0xffffffffu, sum, off);
        sumsq += __shfl_down_sync(0xffffffffu, sumsq, off);
    }
    int w = t >> 5, l = t & 31;
    if (l == 0) { ssum[w] = sum; ssq[w] = sumsq; }
    __syncthreads();
    __shared__ float s_mu, s_rstd;
    if (t == 0) {
        float S = 0.f, Q = 0.f;
#pragma unroll
        for (int i = 0; i < 8; i++) { S += ssum[i]; Q += ssq[i]; }
        float mu = S * (1.0f / POOLD);
        float var = Q * (1.0f / POOLD) - mu * mu;
        s_mu = mu;
        s_rstd = rsqrtf(var + 1e-5f);
    }
    __syncthreads();
    float mu = s_mu, rstd = s_rstd;
    float* hr = h + (size_t)n * POOLD;
#pragma unroll
    for (int jj = 0; jj < 4; jj++) {
        int j = jj * 256 + t;
        hr[j] = (m[jj] - mu) * rstd * g[j] + b[j];
    }
}

// ---------------- pipelined tf32 tensor GEMM: C = act(A @ B + bias) ------------
// Block tile 128x128x32, 2-stage cp.async pipeline, 256 threads = 8 warps
// (2 M x 4 N), warp tile 64x32. Requires N % 128 == 0, K % 32 == 0.
// Dynamic smem: As[2][128][36] + Bs[2][32][132] floats = 70656 bytes.
#define ASTG (128 * 36)
#define BSTG (32 * 132)
#define GEMM_SMEM_BYTES ((2 * ASTG + 2 * BSTG) * 4)

__device__ __forceinline__ void cp16(uint32_t sdst, const float* gsrc, int pred_bytes) {
    asm volatile("cp.async.cg.shared.global [%0], [%1], 16, %2;"
                 :: "r"(sdst), "l"(gsrc), "r"(pred_bytes));
}

__global__ __launch_bounds__(256, 2) void tf32_gemm_pipe(
    const float* __restrict__ A, const float* __restrict__ B,
    const float* __restrict__ bias, float* __restrict__ C,
    int M, int N, int K, int do_elu) {
    extern __shared__ float smem[];
    float* AsBase = smem;                 // 2 stages of [128][36]
    float* BsBase = smem + 2 * ASTG;      // 2 stages of [32][132]

    int tid = threadIdx.x;
    int warp = tid >> 5, lane = tid & 31;
    int lg = lane >> 2, lq = lane & 3;
    int warpM = warp & 1, warpN = warp >> 1;
    int Rw = warpM * 64, Cw = warpN * 32;
    int rowBase = blockIdx.y * 128;       // y = row tile (slow)
    int colBase = blockIdx.x * 128;       // x = col tile (fast -> L2 reuse of A)

    float acc[4][4][4];
#pragma unroll
    for (int mt = 0; mt < 4; mt++)
#pragma unroll
        for (int nt = 0; nt < 4; nt++)
#pragma unroll
            for (int r = 0; r < 4; r++) acc[mt][nt][r] = 0.f;

    int iters = K >> 5;

    // per-thread static load coordinates
    int aRow = tid >> 1;                  // with i-loop: rows 0..127 (2 chunks each)
    int aCh0 = (tid & 1) * 4;             // chunk pairs handled below
    (void)aRow; (void)aCh0;

    uint32_t sA = (uint32_t)__cvta_generic_to_shared(AsBase);
    uint32_t sB = (uint32_t)__cvta_generic_to_shared(BsBase);

#define LOAD_STAGE(IT)                                                          \
    do {                                                                        \
        int k0 = (IT) * 32;                                                     \
        int buf = (IT) & 1;                                                     \
        uint32_t aBuf = sA + buf * (ASTG * 4);                                  \
        uint32_t bBuf = sB + buf * (BSTG * 4);                                  \
        _Pragma("unroll")                                                       \
        for (int i = 0; i < 4; i++) {                                           \
            int idx = i * 256 + tid;          /* [0,1024) */                    \
            int row = idx >> 3, ch = idx & 7;                                   \
            int grow = rowBase + row;                                           \
            const float* src = A + (size_t)grow * K + k0 + ch * 4;              \
            cp16(aBuf + (row * 36 + ch * 4) * 4, src, grow < M ? 16 : 0);       \
        }                                                                       \
        _Pragma("unroll")                                                       \
        for (int i = 0; i < 4; i++) {                                           \
            int idx = i * 256 + tid;          /* [0,1024) */                    \
            int row = idx >> 5, ch = idx & 31;                                  \
            const float* src = B + (size_t)(k0 + row) * N + colBase + ch * 4;   \
            cp16(bBuf + (row * 132 + ch * 4) * 4, src, 16);                     \
        }                                                                       \
        asm volatile("cp.async.commit_group;");                                 \
    } while (0)

    LOAD_STAGE(0);

    for (int it = 0; it < iters; it++) {
        if (it + 1 < iters) {
            LOAD_STAGE(it + 1);
            asm volatile("cp.async.wait_group 1;");
        } else {
            asm volatile("cp.async.wait_group 0;");
        }
        __syncthreads();

        const float* Asb = AsBase + (it & 1) * ASTG;
        const float* Bsb = BsBase + (it & 1) * BSTG;
#pragma unroll
        for (int kk = 0; kk < 32; kk += 8) {
            unsigned a[4][4], bfr[4][2];
#pragma unroll
            for (int mt = 0; mt < 4; mt++) {
                int r0 = Rw + mt * 16 + lg;
                a[mt][0] = f2tf32(Asb[r0 * 36 + kk + lq]);
                a[mt][1] = f2tf32(Asb[(r0 + 8) * 36 + kk + lq]);
                a[mt][2] = f2tf32(Asb[r0 * 36 + kk + lq + 4]);
                a[mt][3] = f2tf32(Asb[(r0 + 8) * 36 + kk + lq + 4]);
            }
#pragma unroll
            for (int nt = 0; nt < 4; nt++) {
                int c0 = Cw + nt * 8 + lg;
                bfr[nt][0] = f2tf32(Bsb[(kk + lq) * 132 + c0]);
                bfr[nt][1] = f2tf32(Bsb[(kk + lq + 4) * 132 + c0]);
            }
#pragma unroll
            for (int mt = 0; mt < 4; mt++)
#pragma unroll
                for (int nt = 0; nt < 4; nt++) {
                    asm volatile(
                        "mma.sync.aligned.m16n8k8.row.col.f32.tf32.tf32.f32 "
                        "{%0,%1,%2,%3}, {%4,%5,%6,%7}, {%8,%9}, {%0,%1,%2,%3};"
                        : "+f"(acc[mt][nt][0]), "+f"(acc[mt][nt][1]),
                          "+f"(acc[mt][nt][2]), "+f"(acc[mt][nt][3])
                        : "r"(a[mt][0]), "r"(a[mt][1]), "r"(a[mt][2]), "r"(a[mt][3]),
                          "r"(bfr[nt][0]), "r"(bfr[nt][1]));
                }
        }
        __syncthreads();
    }
#undef LOAD_STAGE

    // ---- epilogue: bias + optional ELU ----
#pragma unroll
    for (int mt = 0; mt < 4; mt++) {
#pragma unroll
        for (int nt = 0; nt < 4; nt++) {
            int col = colBase + Cw + nt * 8 + lq * 2;
            float b0 = bias[col], b1 = bias[col + 1];
            int r0 = rowBase + Rw + mt * 16 + lg;
            if (r0 < M) {
                float v0 = acc[mt][nt][0] + b0;
                float v1 = acc[mt][nt][1] + b1;
                if (do_elu) { v0 = elu1(v0); v1 = elu1(v1); }
                *(float2*)&C[(size_t)r0 * N + col] = make_float2(v0, v1);
            }
            int r1 = r0 + 8;
            if (r1 < M) {
                float v2 = acc[mt][nt][2] + b0;
                float v3 = acc[mt][nt][3] + b1;
                if (do_elu) { v2 = elu1(v2); v3 = elu1(v3); }
                *(float2*)&C[(size_t)r1 * N + col] = make_float2(v2, v3);
            }
        }
    }
}

// ---------------- tiled fp32 SGEMM (kept for the small 128->64 layer) ----------
#define BM 128
#define BN 64
#define BK 16
#define TM 8
#define TN 4

__global__ __launch_bounds__(256) void sgemm_bias_act(
    const float* __restrict__ A, const float* __restrict__ B,
    const float* __restrict__ bias, float* __restrict__ C,
    int M, int N, int K, int do_elu) {
    __shared__ float As[BK][BM + 4];
    __shared__ float Bs[BK][BN];
    int tid = threadIdx.x;
    int tx = tid & 15, ty = tid >> 4;
    int rowBase = blockIdx.x * BM;
    int colBase = blockIdx.y * BN;

    float acc[TM][TN];
#pragma unroll
    for (int i = 0; i < TM; i++)
#pragma unroll
        for (int j = 0; j < TN; j++) acc[i][j] = 0.f;

    int ar = tid >> 2;
    int ac = (tid & 3) * 4;
    int br = tid >> 4;
    int bc = (tid & 15) * 4;

    for (int k0 = 0; k0 < K; k0 += BK) {
#pragma unroll
        for (int gidx = 0; gidx < 2; gidx++) {
            int r = ar + gidx * 64;
            int grow = rowBase + r;
            float4 v = make_float4(0.f, 0.f, 0.f, 0.f);
            if (grow < M) v = *(const float4*)&A[(size_t)grow * K + k0 + ac];
            As[ac + 0][r] = v.x; As[ac + 1][r] = v.y;
            As[ac + 2][r] = v.z; As[ac + 3][r] = v.w;
        }
        {
            float4 v = *(const float4*)&B[(size_t)(k0 + br) * N + colBase + bc];
            Bs[br][bc + 0] = v.x; Bs[br][bc + 1] = v.y;
            Bs[br][bc + 2] = v.z; Bs[br][bc + 3] = v.w;
        }
        __syncthreads();
#pragma unroll
        for (int k = 0; k < BK; k++) {
            float ra[TM], rb[TN];
#pragma unroll
            for (int i = 0; i < TM; i++) ra[i] = As[k][ty * TM + i];
#pragma unroll
            for (int j = 0; j < TN; j++) rb[j] = Bs[k][tx * TN + j];
#pragma unroll
            for (int i = 0; i < TM; i++)
#pragma unroll
                for (int j = 0; j < TN; j++) acc[i][j] += ra[i] * rb[j];
        }
        __syncthreads();
    }
#pragma unroll
    for (int i = 0; i < TM; i++) {
        int grow = rowBase + ty * TM + i;
        if (grow >= M) continue;
#pragma unroll
        for (int j = 0; j < TN; j++) {
            int gcol = colBase + tx * TN + j;
            float v = acc[i][j] + bias[gcol];
            if (do_elu) v = elu1(v);
            C[(size_t)grow * N + gcol] = v;
        }
    }
}

// ---------------- GCN1: xw = h2 @ c1w (64->32), + self-loop init ----------------
__global__ __launch_bounds__(256) void gcn_xw1_kernel(
    const float* __restrict__ h2, const float* __restrict__ W,  // 64x32
    const float* __restrict__ dinv,
    float* __restrict__ xw, float* __restrict__ outbuf) {
    __shared__ float sW[64 * 32];
    int tid = threadIdx.x;
    for (int i = tid; i < 64 * 32; i += 256) sW[i] = W[i];
    __syncthreads();
    int warp = tid >> 5, lane = tid & 31;
    int n = blockIdx.x * 8 + warp;
    if (n >= N_NODES) return;
    const float* row = h2 + (size_t)n * 64;
    float r0 = row[lane], r1 = row[lane + 32];
    float accv = 0.f;
#pragma unroll
    for (int k = 0; k < 32; k++) {
        float a = __shfl_sync(0xffffffffu, r0, k);
        accv += a * sW[k * 32 + lane];
    }
#pragma unroll
    for (int k = 0; k < 32; k++) {
        float a = __shfl_sync(0xffffffffu, r1, k);
        accv += a * sW[(k + 32) * 32 + lane];
    }
    float di = dinv[n];
    xw[(size_t)n * 32 + lane] = accv;
    outbuf[(size_t)n * 32 + lane] = accv * di * di;
}

// scatter: out[dst] += xw[src]*dinv[src]*dinv[dst], 8 lanes/edge, red.v4
__global__ void gcn_scatter32_kernel(const int* __restrict__ src,
                                     const int* __restrict__ dst,
                                     const float* __restrict__ dinv,
                                     const float* __restrict__ xw,
                                     float* __restrict__ outbuf, int E) {
    int idx = blockIdx.x * blockDim.x + threadIdx.x;
    int e = idx >> 3, q = idx & 7;
    if (e >= E) return;
    int s = src[e], d = dst[e];
    float w = dinv[s] * dinv[d];
    float4 v = *(const float4*)&xw[(size_t)s * 32 + q * 4];
    v.x *= w; v.y *= w; v.z *= w; v.w *= w;
    float* p = &outbuf[(size_t)d * 32 + q * 4];
    asm volatile("red.global.add.v4.f32 [%0], {%1,%2,%3,%4};"
                 :: "l"(p), "f"(v.x), "f"(v.y), "f"(v.z), "f"(v.w) : "memory");
}

__global__ void bias_elu32_kernel(float* __restrict__ buf,
                                  const float* __restrict__ bias, int total) {
    int i = blockIdx.x * blockDim.x + threadIdx.x;
    if (i < total) {
        float v = buf[i] + bias[i & 31];
        buf[i] = elu1(v);
    }
}

// ---------------- GCN2: xw2 = act1 @ c2w (32->16), + self-loop init -------------
__global__ __launch_bounds__(256) void gcn_xw2_kernel(
    const float* __restrict__ g1, const float* __restrict__ W,  // 32x16
    const float* __restrict__ dinv,
    float* __restrict__ xw, float* __restrict__ outbuf) {
    __shared__ float sW[32 * 16];
    int tid = threadIdx.x;
    for (int i = tid; i < 32 * 16; i += 256) sW[i] = W[i];
    __syncthreads();
    int warp = tid >> 5, lane = tid & 31;
    int n = blockIdx.x * 8 + warp;
    if (n >= N_NODES) return;
    float r = g1[(size_t)n * 32 + lane];
    float accv = 0.f;
#pragma unroll
    for (int k = 0; k < 32; k++) {
        float a = __shfl_sync(0xffffffffu, r, k);
        if (lane < 16) accv += a * sW[k * 16 + lane];
    }
    if (lane < 16) {
        float di = dinv[n];
        xw[(size_t)n * 16 + lane] = accv;
        outbuf[(size_t)n * 16 + lane] = accv * di * di;
    }
}

__global__ void gcn_scatter16_kernel(const int* __restrict__ src,
                                     const int* __restrict__ dst,
                                     const float* __restrict__ dinv,
                                     const float* __restrict__ xw,
                                     float* __restrict__ outbuf, int E) {
    int idx = blockIdx.x * blockDim.x + threadIdx.x;
    int e = idx >> 2, q = idx & 3;
    if (e >= E) return;
    int s = src[e], d = dst[e];
    float w = dinv[s] * dinv[d];
    float4 v = *(const float4*)&xw[(size_t)s * 16 + q * 4];
    v.x *= w; v.y *= w; v.z *= w; v.w *= w;
    float* p = &outbuf[(size_t)d * 16 + q * 4];
    asm volatile("red.global.add.v4.f32 [%0], {%1,%2,%3,%4};"
                 :: "l"(p), "f"(v.x), "f"(v.y), "f"(v.z), "f"(v.w) : "memory");
}

// ---------------- edge head -----------------------------------------------------
__global__ __launch_bounds__(256) void edge_head_kernel(
    const int* __restrict__ ei, const int* __restrict__ mask,
    const float* __restrict__ z, const float* __restrict__ c2b,
    const float* __restrict__ lw1, const float* __restrict__ lb1,
    const float* __restrict__ lw2, const float* __restrict__ lb2,
    float* __restrict__ out, int nsel, int E) {
    __shared__ float sW1[32 * 16], sB1[16], sW2[16 * 2], sB2[2], sCB[16];
    int tid = threadIdx.x;
    for (int i = tid; i < 512; i += 256) sW1[i] = lw1[i];
    if (tid < 16) { sB1[tid] = lb1[tid]; sCB[tid] = c2b[tid]; }
    if (tid < 32) sW2[tid] = lw2[tid];
    if (tid < 2)  sB2[tid] = lb2[tid];
    __syncthreads();
    int j = blockIdx.x * 256 + tid;
    if (j >= nsel) return;
    int idx = mask[j];
    int s = ei[idx], d = ei[E + idx];
    float e[32];
#pragma unroll
    for (int k = 0; k < 16; k++) e[k]      = z[(size_t)s * 16 + k] + sCB[k];
#pragma unroll
    for (int k = 0; k < 16; k++) e[16 + k] = z[(size_t)d * 16 + k] + sCB[k];
    float a1[16];
#pragma unroll
    for (int q = 0; q < 16; q++) {
        float accv = sB1[q];
#pragma unroll
        for (int k = 0; k < 32; k++) accv += e[k] * sW1[k * 16 + q];
        a1[q] = elu1(accv);
    }
    float o0 = sB2[0], o1 = sB2[1];
#pragma unroll
    for (int q = 0; q < 16; q++) {
        o0 += a1[q] * sW2[q * 2 + 0];
        o1 += a1[q] * sW2[q * 2 + 1];
    }
    out[(size_t)j * 2 + 0] = o0;
    out[(size_t)j * 2 + 1] = o1;
}

// ---------------- launch --------------------------------------------------------
extern "C" void kernel_launch(void* const* d_in, const int* in_sizes, int n_in,
                              void* d_out, int out_size) {
    const float* x    = (const float*)d_in[0];
    const int*   ei   = (const int*)d_in[1];
    const int*   mask = (const int*)d_in[2];
    const float* ln_g = (const float*)d_in[3];
    const float* ln_b = (const float*)d_in[4];
    const float* w0   = (const float*)d_in[5];
    const float* b0   = (const float*)d_in[6];
    const float* w1   = (const float*)d_in[7];
    const float* b1   = (const float*)d_in[8];
    const float* w2   = (const float*)d_in[9];
    const float* b2   = (const float*)d_in[10];
    const float* c1w  = (const float*)d_in[11];
    const float* c1b  = (const float*)d_in[12];
    const float* c2w  = (const float*)d_in[13];
    const float* c2b  = (const float*)d_in[14];
    const float* lw1  = (const float*)d_in[15];
    const float* lb1  = (const float*)d_in[16];
    const float* lw2  = (const float*)d_in[17];
    const float* lb2  = (const float*)d_in[18];

    int E    = in_sizes[1] / 2;
    int nsel = in_sizes[2];

    float *h, *h0, *h1, *h2, *xw1, *ac1, *xw2, *ac2, *dinv;
    cudaGetSymbolAddress((void**)&h,   g_h);
    cudaGetSymbolAddress((void**)&h0,  g_h0);
    cudaGetSymbolAddress((void**)&h1,  g_h1);
    cudaGetSymbolAddress((void**)&h2,  g_h2);
    cudaGetSymbolAddress((void**)&xw1, g_xw1);
    cudaGetSymbolAddress((void**)&ac1, g_ac1);
    cudaGetSymbolAddress((void**)&xw2, g_xw2);
    cudaGetSymbolAddress((void**)&ac2, g_ac2);
    cudaGetSymbolAddress((void**)&dinv, g_dinv);

    static int smem_set = 0;
    if (!smem_set) {
        cudaFuncSetAttribute(tf32_gemm_pipe,
                             cudaFuncAttributeMaxDynamicSharedMemorySize,
                             GEMM_SMEM_BYTES);
        smem_set = 1;
    }

    const int T = 256;
    // degrees
    deg_init_kernel<<<(N_NODES + T - 1) / T, T>>>(dinv);
    deg_accum_kernel<<<(E + T - 1) / T, T>>>(ei + E, dinv, E);
    deg_final_kernel<<<(N_NODES + T - 1) / T, T>>>(dinv);

    // maxpool + layernorm
    pool_ln_kernel<<<N_NODES, 256>>>(x, ln_g, ln_b, h);

    // MLP stack: big two layers on pipelined tf32 tensor cores
    {
        dim3 grid(512 / 128, (N_NODES + 127) / 128);
        tf32_gemm_pipe<<<grid, 256, GEMM_SMEM_BYTES>>>(h, w0, b0, h0, N_NODES, 512, 1024, 1);
    }
    {
        dim3 grid(128 / 128, (N_NODES + 127) / 128);
        tf32_gemm_pipe<<<grid, 256, GEMM_SMEM_BYTES>>>(h0, w1, b1, h1, N_NODES, 128, 512, 1);
    }
    {
        dim3 grid((N_NODES + BM - 1) / BM, 64 / BN);
        sgemm_bias_act<<<grid, 256>>>(h1, w2, b2, h2, N_NODES, 64, 128, 1);
    }

    // GCN conv 1 (64->32)
    gcn_xw1_kernel<<<(N_NODES + 7) / 8, 256>>>(h2, c1w, dinv, xw1, ac1);
    {
        long long tot = (long long)E * 8;
        gcn_scatter32_kernel<<<(int)((tot + T - 1) / T), T>>>(ei, ei + E, dinv, xw1, ac1, E);
    }
    bias_elu32_kernel<<<(N_NODES * 32 + T - 1) / T, T>>>(ac1, c1b, N_NODES * 32);

    // GCN conv 2 (32->16)
    gcn_xw2_kernel<<<(N_NODES + 7) / 8, 256>>>(ac1, c2w, dinv, xw2, ac2);
    {
        long long tot = (long long)E * 4;
        gcn_scatter16_kernel<<<(int)((tot + T - 1) / T), T>>>(ei, ei + E, dinv, xw2, ac2, E);
    }

    // edge head
    edge_head_kernel<<<(nsel + 255) / 256, 256>>>(ei, mask, ac2, c2b, lw1, lb1, lw2,
                                                  lb2, (float*)d_out, nsel, E);
}

// round 7
// speedup vs baseline: 2.4964x; 1.0262x over previous
#include <cuda_runtime.h>
#include <cuda_bf16.h>
#include <math.h>
#include <stdint.h>

#define N_NODES 50000
#define F_IN    2048
#define POOLD   1024

// ---------------- scratch (static device globals; no allocations) -------------
__device__ float g_h  [(size_t)N_NODES * 1024];  // pooled+LN
__device__ float g_h0 [(size_t)N_NODES * 512];
__device__ float g_h1 [(size_t)N_NODES * 128];
__device__ float g_h2 [(size_t)N_NODES * 64];
__device__ float g_xw1[(size_t)N_NODES * 32];
__device__ float g_ac1[(size_t)N_NODES * 32];    // gcn1 accumulator (raw, pre-act)
__device__ float g_xw2[(size_t)N_NODES * 16];
__device__ float g_ac2[(size_t)N_NODES * 16];    // gcn2 accumulator (z before bias)
__device__ float g_dinv[N_NODES];                 // deg -> rsqrt(deg)

__device__ __forceinline__ float elu1(float v) { return v > 0.f ? v : expm1f(v); }

__device__ __forceinline__ unsigned f2tf32(float v) {
    unsigned r;
    asm("cvt.rna.tf32.f32 %0, %1;" : "=r"(r) : "f"(v));
    return r;
}

// ---------------- degree ------------------------------------------------------
__global__ void deg_init_kernel(float* deg) {
    int i = blockIdx.x * blockDim.x + threadIdx.x;
    if (i < N_NODES) deg[i] = 1.0f;  // self loop
}
__global__ void deg_accum_kernel(const int* __restrict__ dst, float* deg, int E) {
    int e = blockIdx.x * blockDim.x + threadIdx.x;
    if (e < E) atomicAdd(&deg[dst[e]], 1.0f);
}
__global__ void deg_final_kernel(float* deg) {
    int i = blockIdx.x * blockDim.x + threadIdx.x;
    if (i < N_NODES) deg[i] = rsqrtf(deg[i]);   // deg >= 1
}

// ---------------- maxpool(2) + layernorm --------------------------------------
__global__ void pool_ln_kernel(const float* __restrict__ x,
                               const float* __restrict__ g,
                               const float* __restrict__ b,
                               float* __restrict__ h) {
    int n = blockIdx.x;
    int t = threadIdx.x;  // 256
    const float2* xr = (const float2*)(x + (size_t)n * F_IN);
    float m[4];
    float sum = 0.f, sumsq = 0.f;
#pragma unroll
    for (int jj = 0; jj < 4; jj++) {
        int j = jj * 256 + t;
        float2 v = xr[j];
        float mm = fmaxf(v.x, v.y);
        m[jj] = mm;
        sum += mm;
        sumsq += mm * mm;
    }
    __shared__ float ssum[8], ssq[8];
#pragma unroll
    for (int off = 16; off > 0; off >>= 1) {
        sum   += __shfl_down_sync(0xffffffffu, sum, off);
        sumsq += __shfl_down_sync(0xffffffffu, sumsq, off);
    }
    int w = t >> 5, l = t & 31;
    if (l == 0) { ssum[w] = sum; ssq[w] = sumsq; }
    __syncthreads();
    __shared__ float s_mu, s_rstd;
    if (t == 0) {
        float S = 0.f, Q = 0.f;
#pragma unroll
        for (int i = 0; i < 8; i++) { S += ssum[i]; Q += ssq[i]; }
        float mu = S * (1.0f / POOLD);
        float var = Q * (1.0f / POOLD) - mu * mu;
        s_mu = mu;
        s_rstd = rsqrtf(var + 1e-5f);
    }
    __syncthreads();
    float mu = s_mu, rstd = s_rstd;
    float* hr = h + (size_t)n * POOLD;
#pragma unroll
    for (int jj = 0; jj < 4; jj++) {
        int j = jj * 256 + t;
        hr[j] = (m[jj] - mu) * rstd * g[j] + b[j];
    }
}

// ---------------- 3-stage pipelined tf32 tensor GEMM ---------------------------
// C = act(A @ B + bias). Block tile 128x128x32, 256 threads = 8 warps (2M x 4N),
// warp tile 64x32. Requires N % 128 == 0, K % 32 == 0.
// smem strides: A 36 (bank-free for frag reads), B 136 (136%32==8 -> bank-free).
#define ASTG (128 * 36)
#define BSTG (32 * 136)
#define NSTAGE 3
#define GEMM_SMEM_BYTES (NSTAGE * (ASTG + BSTG) * 4)

__device__ __forceinline__ void cp16(uint32_t sdst, const float* gsrc, int pred_bytes) {
    asm volatile("cp.async.cg.shared.global [%0], [%1], 16, %2;"
                 :: "r"(sdst), "l"(gsrc), "r"(pred_bytes));
}

__global__ __launch_bounds__(256, 2) void tf32_gemm_pipe(
    const float* __restrict__ A, const float* __restrict__ B,
    const float* __restrict__ bias, float* __restrict__ C,
    int M, int N, int K, int do_elu) {
    extern __shared__ float smem[];
    float* AsBase = smem;                     // NSTAGE x [128][36]
    float* BsBase = smem + NSTAGE * ASTG;     // NSTAGE x [32][136]

    int tid = threadIdx.x;
    int warp = tid >> 5, lane = tid & 31;
    int lg = lane >> 2, lq = lane & 3;
    int warpM = warp & 1, warpN = warp >> 1;
    int Rw = warpM * 64, Cw = warpN * 32;
    int rowBase = blockIdx.y * 128;       // y = row tile (slow)
    int colBase = blockIdx.x * 128;       // x = col tile (fast -> L2 reuse of A)

    float acc[4][4][4];
#pragma unroll
    for (int mt = 0; mt < 4; mt++)
#pragma unroll
        for (int nt = 0; nt < 4; nt++)
#pragma unroll
            for (int r = 0; r < 4; r++) acc[mt][nt][r] = 0.f;

    int iters = K >> 5;

    uint32_t sA = (uint32_t)__cvta_generic_to_shared(AsBase);
    uint32_t sB = (uint32_t)__cvta_generic_to_shared(BsBase);

#define LOAD_STAGE(IT)                                                          \
    do {                                                                        \
        int k0 = (IT) * 32;                                                     \
        int buf = (IT) % NSTAGE;                                                \
        uint32_t aBuf = sA + buf * (ASTG * 4);                                  \
        uint32_t bBuf = sB + buf * (BSTG * 4);                                  \
        _Pragma("unroll")                                                       \
        for (int i = 0; i < 4; i++) {                                           \
            int idx = i * 256 + tid;          /* [0,1024) */                    \
            int row = idx >> 3, ch = idx & 7;                                   \
            int grow = rowBase + row;                                           \
            const float* src = A + (size_t)grow * K + k0 + ch * 4;              \
            cp16(aBuf + (row * 36 + ch * 4) * 4, src, grow < M ? 16 : 0);       \
        }                                                                       \
        _Pragma("unroll")                                                       \
        for (int i = 0; i < 4; i++) {                                           \
            int idx = i * 256 + tid;          /* [0,1024) */                    \
            int row = idx >> 5, ch = idx & 31;                                  \
            const float* src = B + (size_t)(k0 + row) * N + colBase + ch * 4;   \
            cp16(bBuf + (row * 136 + ch * 4) * 4, src, 16);                     \
        }                                                                       \
        asm volatile("cp.async.commit_group;");                                 \
    } while (0)

    LOAD_STAGE(0);
    if (iters > 1) LOAD_STAGE(1);

    for (int it = 0; it < iters; it++) {
        if (it + 2 < iters) {
            LOAD_STAGE(it + 2);
            asm volatile("cp.async.wait_group 2;");
        } else if (it + 1 < iters) {
            asm volatile("cp.async.wait_group 1;");
        } else {
            asm volatile("cp.async.wait_group 0;");
        }
        __syncthreads();

        const float* Asb = AsBase + (it % NSTAGE) * ASTG;
        const float* Bsb = BsBase + (it % NSTAGE) * BSTG;
#pragma unroll
        for (int kk = 0; kk < 32; kk += 8) {
            unsigned a[4][4], bfr[4][2];
#pragma unroll
            for (int mt = 0; mt < 4; mt++) {
                int r0 = Rw + mt * 16 + lg;
                a[mt][0] = f2tf32(Asb[r0 * 36 + kk + lq]);
                a[mt][1] = f2tf32(Asb[(r0 + 8) * 36 + kk + lq]);
                a[mt][2] = f2tf32(Asb[r0 * 36 + kk + lq + 4]);
                a[mt][3] = f2tf32(Asb[(r0 + 8) * 36 + kk + lq + 4]);
            }
#pragma unroll
            for (int nt = 0; nt < 4; nt++) {
                int c0 = Cw + nt * 8 + lg;
                bfr[nt][0] = f2tf32(Bsb[(kk + lq) * 136 + c0]);
                bfr[nt][1] = f2tf32(Bsb[(kk + lq + 4) * 136 + c0]);
            }
#pragma unroll
            for (int mt = 0; mt < 4; mt++)
#pragma unroll
                for (int nt = 0; nt < 4; nt++) {
                    asm volatile(
                        "mma.sync.aligned.m16n8k8.row.col.f32.tf32.tf32.f32 "
                        "{%0,%1,%2,%3}, {%4,%5,%6,%7}, {%8,%9}, {%0,%1,%2,%3};"
                        : "+f"(acc[mt][nt][0]), "+f"(acc[mt][nt][1]),
                          "+f"(acc[mt][nt][2]), "+f"(acc[mt][nt][3])
                        : "r"(a[mt][0]), "r"(a[mt][1]), "r"(a[mt][2]), "r"(a[mt][3]),
                          "r"(bfr[nt][0]), "r"(bfr[nt][1]));
                }
        }
        __syncthreads();
    }
#undef LOAD_STAGE

    // ---- epilogue: bias + optional ELU ----
#pragma unroll
    for (int mt = 0; mt < 4; mt++) {
#pragma unroll
        for (int nt = 0; nt < 4; nt++) {
            int col = colBase + Cw + nt * 8 + lq * 2;
            float b0 = bias[col], b1 = bias[col + 1];
            int r0 = rowBase + Rw + mt * 16 + lg;
            if (r0 < M) {
                float v0 = acc[mt][nt][0] + b0;
                float v1 = acc[mt][nt][1] + b1;
                if (do_elu) { v0 = elu1(v0); v1 = elu1(v1); }
                *(float2*)&C[(size_t)r0 * N + col] = make_float2(v0, v1);
            }
            int r1 = r0 + 8;
            if (r1 < M) {
                float v2 = acc[mt][nt][2] + b0;
                float v3 = acc[mt][nt][3] + b1;
                if (do_elu) { v2 = elu1(v2); v3 = elu1(v3); }
                *(float2*)&C[(size_t)r1 * N + col] = make_float2(v2, v3);
            }
        }
    }
}

// ---------------- tiled fp32 SGEMM (kept for the small 128->64 layer) ----------
#define BM 128
#define BN 64
#define BK 16
#define TM 8
#define TN 4

__global__ __launch_bounds__(256) void sgemm_bias_act(
    const float* __restrict__ A, const float* __restrict__ B,
    const float* __restrict__ bias, float* __restrict__ C,
    int M, int N, int K, int do_elu) {
    __shared__ float As[BK][BM + 4];
    __shared__ float Bs[BK][BN];
    int tid = threadIdx.x;
    int tx = tid & 15, ty = tid >> 4;
    int rowBase = blockIdx.x * BM;
    int colBase = blockIdx.y * BN;

    float acc[TM][TN];
#pragma unroll
    for (int i = 0; i < TM; i++)
#pragma unroll
        for (int j = 0; j < TN; j++) acc[i][j] = 0.f;

    int ar = tid >> 2;
    int ac = (tid & 3) * 4;
    int br = tid >> 4;
    int bc = (tid & 15) * 4;

    for (int k0 = 0; k0 < K; k0 += BK) {
#pragma unroll
        for (int gidx = 0; gidx < 2; gidx++) {
            int r = ar + gidx * 64;
            int grow = rowBase + r;
            float4 v = make_float4(0.f, 0.f, 0.f, 0.f);
            if (grow < M) v = *(const float4*)&A[(size_t)grow * K + k0 + ac];
            As[ac + 0][r] = v.x; As[ac + 1][r] = v.y;
            As[ac + 2][r] = v.z; As[ac + 3][r] = v.w;
        }
        {
            float4 v = *(const float4*)&B[(size_t)(k0 + br) * N + colBase + bc];
            Bs[br][bc + 0] = v.x; Bs[br][bc + 1] = v.y;
            Bs[br][bc + 2] = v.z; Bs[br][bc + 3] = v.w;
        }
        __syncthreads();
#pragma unroll
        for (int k = 0; k < BK; k++) {
            float ra[TM], rb[TN];
#pragma unroll
            for (int i = 0; i < TM; i++) ra[i] = As[k][ty * TM + i];
#pragma unroll
            for (int j = 0; j < TN; j++) rb[j] = Bs[k][tx * TN + j];
#pragma unroll
            for (int i = 0; i < TM; i++)
#pragma unroll
                for (int j = 0; j < TN; j++) acc[i][j] += ra[i] * rb[j];
        }
        __syncthreads();
    }
#pragma unroll
    for (int i = 0; i < TM; i++) {
        int grow = rowBase + ty * TM + i;
        if (grow >= M) continue;
#pragma unroll
        for (int j = 0; j < TN; j++) {
            int gcol = colBase + tx * TN + j;
            float v = acc[i][j] + bias[gcol];
            if (do_elu) v = elu1(v);
            C[(size_t)grow * N + gcol] = v;
        }
    }
}

// ---------------- GCN1: xw = h2 @ c1w (64->32), + self-loop init ----------------
__global__ __launch_bounds__(256) void gcn_xw1_kernel(
    const float* __restrict__ h2, const float* __restrict__ W,  // 64x32
    const float* __restrict__ dinv,
    float* __restrict__ xw, float* __restrict__ outbuf) {
    __shared__ float sW[64 * 32];
    int tid = threadIdx.x;
    for (int i = tid; i < 64 * 32; i += 256) sW[i] = W[i];
    __syncthreads();
    int warp = tid >> 5, lane = tid & 31;
    int n = blockIdx.x * 8 + warp;
    if (n >= N_NODES) return;
    const float* row = h2 + (size_t)n * 64;
    float r0 = row[lane], r1 = row[lane + 32];
    float accv = 0.f;
#pragma unroll
    for (int k = 0; k < 32; k++) {
        float a = __shfl_sync(0xffffffffu, r0, k);
        accv += a * sW[k * 32 + lane];
    }
#pragma unroll
    for (int k = 0; k < 32; k++) {
        float a = __shfl_sync(0xffffffffu, r1, k);
        accv += a * sW[(k + 32) * 32 + lane];
    }
    float di = dinv[n];
    xw[(size_t)n * 32 + lane] = accv;
    outbuf[(size_t)n * 32 + lane] = accv * di * di;
}

// scatter: out[dst] += xw[src]*dinv[src]*dinv[dst], 8 lanes/edge, red.v4
__global__ void gcn_scatter32_kernel(const int* __restrict__ src,
                                     const int* __restrict__ dst,
                                     const float* __restrict__ dinv,
                                     const float* __restrict__ xw,
                                     float* __restrict__ outbuf, int E) {
    int idx = blockIdx.x * blockDim.x + threadIdx.x;
    int e = idx >> 3, q = idx & 7;
    if (e >= E) return;
    int s = src[e], d = dst[e];
    float w = dinv[s] * dinv[d];
    float4 v = *(const float4*)&xw[(size_t)s * 32 + q * 4];
    v.x *= w; v.y *= w; v.z *= w; v.w *= w;
    float* p = &outbuf[(size_t)d * 32 + q * 4];
    asm volatile("red.global.add.v4.f32 [%0], {%1,%2,%3,%4};"
                 :: "l"(p), "f"(v.x), "f"(v.y), "f"(v.z), "f"(v.w) : "memory");
}

// ---------------- GCN2: xw2 = elu(ac1 + c1b) @ c2w (32->16), fused activation ----
__global__ __launch_bounds__(256) void gcn_xw2_kernel(
    const float* __restrict__ g1raw, const float* __restrict__ c1b,
    const float* __restrict__ W,  // 32x16
    const float* __restrict__ dinv,
    float* __restrict__ xw, float* __restrict__ outbuf) {
    __shared__ float sW[32 * 16];
    __shared__ float sB[32];
    int tid = threadIdx.x;
    for (int i = tid; i < 32 * 16; i += 256) sW[i] = W[i];
    if (tid < 32) sB[tid] = c1b[tid];
    __syncthreads();
    int warp = tid >> 5, lane = tid & 31;
    int n = blockIdx.x * 8 + warp;
    if (n >= N_NODES) return;
    float r = elu1(g1raw[(size_t)n * 32 + lane] + sB[lane]);
    float accv = 0.f;
#pragma unroll
    for (int k = 0; k < 32; k++) {
        float a = __shfl_sync(0xffffffffu, r, k);
        if (lane < 16) accv += a * sW[k * 16 + lane];
    }
    if (lane < 16) {
        float di = dinv[n];
        xw[(size_t)n * 16 + lane] = accv;
        outbuf[(size_t)n * 16 + lane] = accv * di * di;
    }
}

__global__ void gcn_scatter16_kernel(const int* __restrict__ src,
                                     const int* __restrict__ dst,
                                     const float* __restrict__ dinv,
                                     const float* __restrict__ xw,
                                     float* __restrict__ outbuf, int E) {
    int idx = blockIdx.x * blockDim.x + threadIdx.x;
    int e = idx >> 2, q = idx & 3;
    if (e >= E) return;
    int s = src[e], d = dst[e];
    float w = dinv[s] * dinv[d];
    float4 v = *(const float4*)&xw[(size_t)s * 16 + q * 4];
    v.x *= w; v.y *= w; v.z *= w; v.w *= w;
    float* p = &outbuf[(size_t)d * 16 + q * 4];
    asm volatile("red.global.add.v4.f32 [%0], {%1,%2,%3,%4};"
                 :: "l"(p), "f"(v.x), "f"(v.y), "f"(v.z), "f"(v.w) : "memory");
}

// ---------------- edge head -----------------------------------------------------
__global__ __launch_bounds__(256) void edge_head_kernel(
    const int* __restrict__ ei, const int* __restrict__ mask,
    const float* __restrict__ z, const float* __restrict__ c2b,
    const float* __restrict__ lw1, const float* __restrict__ lb1,
    const float* __restrict__ lw2, const float* __restrict__ lb2,
    float* __restrict__ out, int nsel, int E) {
    __shared__ float sW1[32 * 16], sB1[16], sW2[16 * 2], sB2[2], sCB[16];
    int tid = threadIdx.x;
    for (int i = tid; i < 512; i += 256) sW1[i] = lw1[i];
    if (tid < 16) { sB1[tid] = lb1[tid]; sCB[tid] = c2b[tid]; }
    if (tid < 32) sW2[tid] = lw2[tid];
    if (tid < 2)  sB2[tid] = lb2[tid];
    __syncthreads();
    int j = blockIdx.x * 256 + tid;
    if (j >= nsel) return;
    int idx = mask[j];
    int s = ei[idx], d = ei[E + idx];
    float e[32];
#pragma unroll
    for (int k = 0; k < 16; k++) e[k]      = z[(size_t)s * 16 + k] + sCB[k];
#pragma unroll
    for (int k = 0; k < 16; k++) e[16 + k] = z[(size_t)d * 16 + k] + sCB[k];
    float a1[16];
#pragma unroll
    for (int q = 0; q < 16; q++) {
        float accv = sB1[q];
#pragma unroll
        for (int k = 0; k < 32; k++) accv += e[k] * sW1[k * 16 + q];
        a1[q] = elu1(accv);
    }
    float o0 = sB2[0], o1 = sB2[1];
#pragma unroll
    for (int q = 0; q < 16; q++) {
        o0 += a1[q] * sW2[q * 2 + 0];
        o1 += a1[q] * sW2[q * 2 + 1];
    }
    out[(size_t)j * 2 + 0] = o0;
    out[(size_t)j * 2 + 1] = o1;
}

// ---------------- launch --------------------------------------------------------
extern "C" void kernel_launch(void* const* d_in, const int* in_sizes, int n_in,
                              void* d_out, int out_size) {
    const float* x    = (const float*)d_in[0];
    const int*   ei   = (const int*)d_in[1];
    const int*   mask = (const int*)d_in[2];
    const float* ln_g = (const float*)d_in[3];
    const float* ln_b = (const float*)d_in[4];
    const float* w0   = (const float*)d_in[5];
    const float* b0   = (const float*)d_in[6];
    const float* w1   = (const float*)d_in[7];
    const float* b1   = (const float*)d_in[8];
    const float* w2   = (const float*)d_in[9];
    const float* b2   = (const float*)d_in[10];
    const float* c1w  = (const float*)d_in[11];
    const float* c1b  = (const float*)d_in[12];
    const float* c2w  = (const float*)d_in[13];
    const float* c2b  = (const float*)d_in[14];
    const float* lw1  = (const float*)d_in[15];
    const float* lb1  = (const float*)d_in[16];
    const float* lw2  = (const float*)d_in[17];
    const float* lb2  = (const float*)d_in[18];

    int E    = in_sizes[1] / 2;
    int nsel = in_sizes[2];

    float *h, *h0, *h1, *h2, *xw1, *ac1, *xw2, *ac2, *dinv;
    cudaGetSymbolAddress((void**)&h,   g_h);
    cudaGetSymbolAddress((void**)&h0,  g_h0);
    cudaGetSymbolAddress((void**)&h1,  g_h1);
    cudaGetSymbolAddress((void**)&h2,  g_h2);
    cudaGetSymbolAddress((void**)&xw1, g_xw1);
    cudaGetSymbolAddress((void**)&ac1, g_ac1);
    cudaGetSymbolAddress((void**)&xw2, g_xw2);
    cudaGetSymbolAddress((void**)&ac2, g_ac2);
    cudaGetSymbolAddress((void**)&dinv, g_dinv);

    static int smem_set = 0;
    if (!smem_set) {
        cudaFuncSetAttribute(tf32_gemm_pipe,
                             cudaFuncAttributeMaxDynamicSharedMemorySize,
                             GEMM_SMEM_BYTES);
        smem_set = 1;
    }

    const int T = 256;
    // degrees
    deg_init_kernel<<<(N_NODES + T - 1) / T, T>>>(dinv);
    deg_accum_kernel<<<(E + T - 1) / T, T>>>(ei + E, dinv, E);
    deg_final_kernel<<<(N_NODES + T - 1) / T, T>>>(dinv);

    // maxpool + layernorm
    pool_ln_kernel<<<N_NODES, 256>>>(x, ln_g, ln_b, h);

    // MLP stack: big two layers on pipelined tf32 tensor cores
    {
        dim3 grid(512 / 128, (N_NODES + 127) / 128);
        tf32_gemm_pipe<<<grid, 256, GEMM_SMEM_BYTES>>>(h, w0, b0, h0, N_NODES, 512, 1024, 1);
    }
    {
        dim3 grid(128 / 128, (N_NODES + 127) / 128);
        tf32_gemm_pipe<<<grid, 256, GEMM_SMEM_BYTES>>>(h0, w1, b1, h1, N_NODES, 128, 512, 1);
    }
    {
        dim3 grid((N_NODES + BM - 1) / BM, 64 / BN);
        sgemm_bias_act<<<grid, 256>>>(h1, w2, b2, h2, N_NODES, 64, 128, 1);
    }

    // GCN conv 1 (64->32)
    gcn_xw1_kernel<<<(N_NODES + 7) / 8, 256>>>(h2, c1w, dinv, xw1, ac1);
    {
        long long tot = (long long)E * 8;
        gcn_scatter32_kernel<<<(int)((tot + T - 1) / T), T>>>(ei, ei + E, dinv, xw1, ac1, E);
    }

    // GCN conv 2 (32->16), bias+ELU of conv1 fused into the load
    gcn_xw2_kernel<<<(N_NODES + 7) / 8, 256>>>(ac1, c1b, c2w, dinv, xw2, ac2);
    {
        long long tot = (long long)E * 4;
        gcn_scatter16_kernel<<<(int)((tot + T - 1) / T), T>>>(ei, ei + E, dinv, xw2, ac2, E);
    }

    // edge head
    edge_head_kernel<<<(nsel + 255) / 256, 256>>>(ei, mask, ac2, c2b, lw1, lb1, lw2,
                                                  lb2, (float*)d_out, nsel, E);
}

// round 8
// speedup vs baseline: 2.5366x; 1.0161x over previous
#include <cuda_runtime.h>
#include <cuda_bf16.h>
#include <math.h>
#include <stdint.h>

#define N_NODES 50000
#define F_IN    2048
#define POOLD   1024

// ---------------- scratch (static device globals; no allocations) -------------
__device__ float g_h  [(size_t)N_NODES * 1024];  // pooled+LN
__device__ float g_h0 [(size_t)N_NODES * 512];
__device__ float g_h1 [(size_t)N_NODES * 128];
__device__ float g_xw1[(size_t)N_NODES * 32];
__device__ float g_ac1[(size_t)N_NODES * 32];    // gcn1 accumulator (raw, pre-act)
__device__ float g_xw2[(size_t)N_NODES * 16];
__device__ float g_ac2[(size_t)N_NODES * 16];    // gcn2 accumulator (z before bias)
__device__ float g_dinv[N_NODES];                 // deg -> rsqrt(deg)

__device__ __forceinline__ float elu1(float v) { return v > 0.f ? v : expm1f(v); }

__device__ __forceinline__ unsigned f2tf32(float v) {
    unsigned r;
    asm("cvt.rna.tf32.f32 %0, %1;" : "=r"(r) : "f"(v));
    return r;
}

// ---------------- side-stream for the degree chain (static ctor: created
// before any harness mem checkpoint, never during capture) --------------------
struct SideStream {
    cudaStream_t s = nullptr;
    cudaEvent_t evFork = nullptr, evJoin = nullptr;
    bool ok = false;
    SideStream() {
        if (cudaStreamCreateWithFlags(&s, cudaStreamNonBlocking) == cudaSuccess &&
            cudaEventCreateWithFlags(&evFork, cudaEventDisableTiming) == cudaSuccess &&
            cudaEventCreateWithFlags(&evJoin, cudaEventDisableTiming) == cudaSuccess)
            ok = true;
    }
};
static SideStream g_ss;

// ---------------- degree ------------------------------------------------------
__global__ void deg_init_kernel(float* deg) {
    int i = blockIdx.x * blockDim.x + threadIdx.x;
    if (i < N_NODES) deg[i] = 1.0f;  // self loop
}
__global__ void deg_accum_kernel(const int* __restrict__ dst, float* deg, int E) {
    int e = blockIdx.x * blockDim.x + threadIdx.x;
    if (e < E) atomicAdd(&deg[dst[e]], 1.0f);
}
__global__ void deg_final_kernel(float* deg) {
    int i = blockIdx.x * blockDim.x + threadIdx.x;
    if (i < N_NODES) deg[i] = rsqrtf(deg[i]);   // deg >= 1
}

// ---------------- maxpool(2) + layernorm (float4 loads) ------------------------
__global__ void pool_ln_kernel(const float* __restrict__ x,
                               const float* __restrict__ g,
                               const float* __restrict__ b,
                               float* __restrict__ h) {
    int n = blockIdx.x;
    int t = threadIdx.x;  // 256
    const float4* xr = (const float4*)(x + (size_t)n * F_IN);
    float m[2][2];
    float sum = 0.f, sumsq = 0.f;
#pragma unroll
    for (int jj = 0; jj < 2; jj++) {
        int j = jj * 256 + t;            // float4 index [0,512)
        float4 v = xr[j];
        float m0 = fmaxf(v.x, v.y);
        float m1 = fmaxf(v.z, v.w);
        m[jj][0] = m0; m[jj][1] = m1;
        sum += m0 + m1;
        sumsq += m0 * m0 + m1 * m1;
    }
    __shared__ float ssum[8], ssq[8];
#pragma unroll
    for (int off = 16; off > 0; off >>= 1) {
        sum   += __shfl_down_sync(0xffffffffu, sum, off);
        sumsq += __shfl_down_sync(0xffffffffu, sumsq, off);
    }
    int w = t >> 5, l = t & 31;
    if (l == 0) { ssum[w] = sum; ssq[w] = sumsq; }
    __syncthreads();
    __shared__ float s_mu, s_rstd;
    if (t == 0) {
        float S = 0.f, Q = 0.f;
#pragma unroll
        for (int i = 0; i < 8; i++) { S += ssum[i]; Q += ssq[i]; }
        float mu = S * (1.0f / POOLD);
        float var = Q * (1.0f / POOLD) - mu * mu;
        s_mu = mu;
        s_rstd = rsqrtf(var + 1e-5f);
    }
    __syncthreads();
    float mu = s_mu, rstd = s_rstd;
    float* hr = h + (size_t)n * POOLD;
#pragma unroll
    for (int jj = 0; jj < 2; jj++) {
        int j = jj * 256 + t;            // pooled pair index
        float o0 = (m[jj][0] - mu) * rstd * g[2 * j] + b[2 * j];
        float o1 = (m[jj][1] - mu) * rstd * g[2 * j + 1] + b[2 * j + 1];
        *(float2*)&hr[2 * j] = make_float2(o0, o1);
    }
}

// ---------------- 3-stage pipelined tf32 tensor GEMM ---------------------------
// C = act(A @ B + bias). Block tile 128x128x32, 256 threads = 8 warps (2M x 4N),
// warp tile 64x32. Requires N % 128 == 0, K % 32 == 0.
#define ASTG (128 * 36)
#define BSTG (32 * 136)
#define NSTAGE 3
#define GEMM_SMEM_BYTES (NSTAGE * (ASTG + BSTG) * 4)

__device__ __forceinline__ void cp16(uint32_t sdst, const float* gsrc, int pred_bytes) {
    asm volatile("cp.async.cg.shared.global [%0], [%1], 16, %2;"
                 :: "r"(sdst), "l"(gsrc), "r"(pred_bytes));
}

__global__ __launch_bounds__(256, 2) void tf32_gemm_pipe(
    const float* __restrict__ A, const float* __restrict__ B,
    const float* __restrict__ bias, float* __restrict__ C,
    int M, int N, int K, int do_elu) {
    extern __shared__ float smem[];
    float* AsBase = smem;                     // NSTAGE x [128][36]
    float* BsBase = smem + NSTAGE * ASTG;     // NSTAGE x [32][136]

    int tid = threadIdx.x;
    int warp = tid >> 5, lane = tid & 31;
    int lg = lane >> 2, lq = lane & 3;
    int warpM = warp & 1, warpN = warp >> 1;
    int Rw = warpM * 64, Cw = warpN * 32;
    int rowBase = blockIdx.y * 128;       // y = row tile (slow)
    int colBase = blockIdx.x * 128;       // x = col tile (fast -> L2 reuse of A)

    float acc[4][4][4];
#pragma unroll
    for (int mt = 0; mt < 4; mt++)
#pragma unroll
        for (int nt = 0; nt < 4; nt++)
#pragma unroll
            for (int r = 0; r < 4; r++) acc[mt][nt][r] = 0.f;

    int iters = K >> 5;

    uint32_t sA = (uint32_t)__cvta_generic_to_shared(AsBase);
    uint32_t sB = (uint32_t)__cvta_generic_to_shared(BsBase);

#define LOAD_STAGE(IT)                                                          \
    do {                                                                        \
        int k0 = (IT) * 32;                                                     \
        int buf = (IT) % NSTAGE;                                                \
        uint32_t aBuf = sA + buf * (ASTG * 4);                                  \
        uint32_t bBuf = sB + buf * (BSTG * 4);                                  \
        _Pragma("unroll")                                                       \
        for (int i = 0; i < 4; i++) {                                           \
            int idx = i * 256 + tid;          /* [0,1024) */                    \
            int row = idx >> 3, ch = idx & 7;                                   \
            int grow = rowBase + row;                                           \
            const float* src = A + (size_t)grow * K + k0 + ch * 4;              \
            cp16(aBuf + (row * 36 + ch * 4) * 4, src, grow < M ? 16 : 0);       \
        }                                                                       \
        _Pragma("unroll")                                                       \
        for (int i = 0; i < 4; i++) {                                           \
            int idx = i * 256 + tid;          /* [0,1024) */                    \
            int row = idx >> 5, ch = idx & 31;                                  \
            const float* src = B + (size_t)(k0 + row) * N + colBase + ch * 4;   \
            cp16(bBuf + (row * 136 + ch * 4) * 4, src, 16);                     \
        }                                                                       \
        asm volatile("cp.async.commit_group;");                                 \
    } while (0)

    LOAD_STAGE(0);
    if (iters > 1) LOAD_STAGE(1);

    for (int it = 0; it < iters; it++) {
        if (it + 2 < iters) {
            LOAD_STAGE(it + 2);
            asm volatile("cp.async.wait_group 2;");
        } else if (it + 1 < iters) {
            asm volatile("cp.async.wait_group 1;");
        } else {
            asm volatile("cp.async.wait_group 0;");
        }
        __syncthreads();

        const float* Asb = AsBase + (it % NSTAGE) * ASTG;
        const float* Bsb = BsBase + (it % NSTAGE) * BSTG;
#pragma unroll
        for (int kk = 0; kk < 32; kk += 8) {
            unsigned a[4][4], bfr[4][2];
#pragma unroll
            for (int mt = 0; mt < 4; mt++) {
                int r0 = Rw + mt * 16 + lg;
                a[mt][0] = f2tf32(Asb[r0 * 36 + kk + lq]);
                a[mt][1] = f2tf32(Asb[(r0 + 8) * 36 + kk + lq]);
                a[mt][2] = f2tf32(Asb[r0 * 36 + kk + lq + 4]);
                a[mt][3] = f2tf32(Asb[(r0 + 8) * 36 + kk + lq + 4]);
            }
#pragma unroll
            for (int nt = 0; nt < 4; nt++) {
                int c0 = Cw + nt * 8 + lg;
                bfr[nt][0] = f2tf32(Bsb[(kk + lq) * 136 + c0]);
                bfr[nt][1] = f2tf32(Bsb[(kk + lq + 4) * 136 + c0]);
            }
#pragma unroll
            for (int mt = 0; mt < 4; mt++)
#pragma unroll
                for (int nt = 0; nt < 4; nt++) {
                    asm volatile(
                        "mma.sync.aligned.m16n8k8.row.col.f32.tf32.tf32.f32 "
                        "{%0,%1,%2,%3}, {%4,%5,%6,%7}, {%8,%9}, {%0,%1,%2,%3};"
                        : "+f"(acc[mt][nt][0]), "+f"(acc[mt][nt][1]),
                          "+f"(acc[mt][nt][2]), "+f"(acc[mt][nt][3])
                        : "r"(a[mt][0]), "r"(a[mt][1]), "r"(a[mt][2]), "r"(a[mt][3]),
                          "r"(bfr[nt][0]), "r"(bfr[nt][1]));
                }
        }
        __syncthreads();
    }
#undef LOAD_STAGE

    // ---- epilogue: bias + optional ELU ----
#pragma unroll
    for (int mt = 0; mt < 4; mt++) {
#pragma unroll
        for (int nt = 0; nt < 4; nt++) {
            int col = colBase + Cw + nt * 8 + lq * 2;
            float b0 = bias[col], b1 = bias[col + 1];
            int r0 = rowBase + Rw + mt * 16 + lg;
            if (r0 < M) {
                float v0 = acc[mt][nt][0] + b0;
                float v1 = acc[mt][nt][1] + b1;
                if (do_elu) { v0 = elu1(v0); v1 = elu1(v1); }
                *(float2*)&C[(size_t)r0 * N + col] = make_float2(v0, v1);
            }
            int r1 = r0 + 8;
            if (r1 < M) {
                float v2 = acc[mt][nt][2] + b0;
                float v3 = acc[mt][nt][3] + b1;
                if (do_elu) { v2 = elu1(v2); v3 = elu1(v3); }
                *(float2*)&C[(size_t)r1 * N + col] = make_float2(v2, v3);
            }
        }
    }
}

// ---------------- fused: h2 = elu(h1 @ w2 + b2); xw1 = h2 @ c1w; self-loop init --
// Block: 256 threads, 128 rows. Stage A: fp32 tile GEMM (identical summation
// order to the previous sgemm_bias_act). Stage B: per-warp shuffle GEMM 64->32.
__global__ __launch_bounds__(256) void mlp3_gcn1_kernel(
    const float* __restrict__ h1,   // [M,128]
    const float* __restrict__ w2,   // [128,64]
    const float* __restrict__ b2,   // [64]
    const float* __restrict__ c1w,  // [64,32]
    const float* __restrict__ dinv,
    float* __restrict__ xw, float* __restrict__ outbuf, int M) {
    __shared__ float sbuf[128 * 68];       // stage A: As(16x132)+Bs(16x64); stage B: h2s(128x68)
    __shared__ float sW[64 * 32];
    __shared__ float sB2[64];

    int tid = threadIdx.x;
    for (int i = tid; i < 64 * 32; i += 256) sW[i] = c1w[i];
    if (tid < 64) sB2[tid] = b2[tid];

    float* As = sbuf;                  // [16][132]
    float* Bs = sbuf + 16 * 132;       // [16][64]

    int tx = tid & 15, ty = tid >> 4;
    int rowBase = blockIdx.x * 128;

    float acc[8][4];
#pragma unroll
    for (int i = 0; i < 8; i++)
#pragma unroll
        for (int j = 0; j < 4; j++) acc[i][j] = 0.f;

    int ar = tid >> 2;
    int ac = (tid & 3) * 4;
    int br = tid >> 4;
    int bc = (tid & 15) * 4;

    for (int k0 = 0; k0 < 128; k0 += 16) {
#pragma unroll
        for (int gidx = 0; gidx < 2; gidx++) {
            int r = ar + gidx * 64;
            int grow = rowBase + r;
            float4 v = make_float4(0.f, 0.f, 0.f, 0.f);
            if (grow < M) v = *(const float4*)&h1[(size_t)grow * 128 + k0 + ac];
            As[(ac + 0) * 132 + r] = v.x; As[(ac + 1) * 132 + r] = v.y;
            As[(ac + 2) * 132 + r] = v.z; As[(ac + 3) * 132 + r] = v.w;
        }
        {
            float4 v = *(const float4*)&w2[(size_t)(k0 + br) * 64 + bc];
            Bs[br * 64 + bc + 0] = v.x; Bs[br * 64 + bc + 1] = v.y;
            Bs[br * 64 + bc + 2] = v.z; Bs[br * 64 + bc + 3] = v.w;
        }
        __syncthreads();
#pragma unroll
        for (int k = 0; k < 16; k++) {
            float ra[8], rb[4];
#pragma unroll
            for (int i = 0; i < 8; i++) ra[i] = As[k * 132 + ty * 8 + i];
#pragma unroll
            for (int j = 0; j < 4; j++) rb[j] = Bs[k * 64 + tx * 4 + j];
#pragma unroll
            for (int i = 0; i < 8; i++)
#pragma unroll
                for (int j = 0; j < 4; j++) acc[i][j] += ra[i] * rb[j];
        }
        __syncthreads();
    }

    // write h2 (elu(acc + b2)) into sbuf as h2s[128][68]
#pragma unroll
    for (int i = 0; i < 8; i++) {
        int row = ty * 8 + i;
#pragma unroll
        for (int j = 0; j < 4; j++) {
            int col = tx * 4 + j;
            sbuf[row * 68 + col] = elu1(acc[i][j] + sB2[col]);
        }
    }
    __syncthreads();

    // Stage B: warp per row (16 rows per warp)
    int warp = tid >> 5, lane = tid & 31;
#pragma unroll 1
    for (int r = 0; r < 16; r++) {
        int row = warp + r * 8;
        int n = rowBase + row;
        if (n >= M) continue;
        float r0 = sbuf[row * 68 + lane], r1 = sbuf[row * 68 + 32 + lane];
        float accv = 0.f;
#pragma unroll
        for (int k = 0; k < 32; k++) {
            float a = __shfl_sync(0xffffffffu, r0, k);
            accv += a * sW[k * 32 + lane];
        }
#pragma unroll
        for (int k = 0; k < 32; k++) {
            float a = __shfl_sync(0xffffffffu, r1, k);
            accv += a * sW[(k + 32) * 32 + lane];
        }
        float di = dinv[n];
        xw[(size_t)n * 32 + lane] = accv;
        outbuf[(size_t)n * 32 + lane] = accv * di * di;
    }
}

// scatter: out[dst] += xw[src]*dinv[src]*dinv[dst], 8 lanes/edge, red.v4
__global__ void gcn_scatter32_kernel(const int* __restrict__ src,
                                     const int* __restrict__ dst,
                                     const float* __restrict__ dinv,
                                     const float* __restrict__ xw,
                                     float* __restrict__ outbuf, int E) {
    int idx = blockIdx.x * blockDim.x + threadIdx.x;
    int e = idx >> 3, q = idx & 7;
    if (e >= E) return;
    int s = src[e], d = dst[e];
    float w = dinv[s] * dinv[d];
    float4 v = *(const float4*)&xw[(size_t)s * 32 + q * 4];
    v.x *= w; v.y *= w; v.z *= w; v.w *= w;
    float* p = &outbuf[(size_t)d * 32 + q * 4];
    asm volatile("red.global.add.v4.f32 [%0], {%1,%2,%3,%4};"
                 :: "l"(p), "f"(v.x), "f"(v.y), "f"(v.z), "f"(v.w) : "memory");
}

// ---------------- GCN2: xw2 = elu(ac1 + c1b) @ c2w (32->16), fused activation ----
__global__ __launch_bounds__(256) void gcn_xw2_kernel(
    const float* __restrict__ g1raw, const float* __restrict__ c1b,
    const float* __restrict__ W,  // 32x16
    const float* __restrict__ dinv,
    float* __restrict__ xw, float* __restrict__ outbuf) {
    __shared__ float sW[32 * 16];
    __shared__ float sB[32];
    int tid = threadIdx.x;
    for (int i = tid; i < 32 * 16; i += 256) sW[i] = W[i];
    if (tid < 32) sB[tid] = c1b[tid];
    __syncthreads();
    int warp = tid >> 5, lane = tid & 31;
    int n = blockIdx.x * 8 + warp;
    if (n >= N_NODES) return;
    float r = elu1(g1raw[(size_t)n * 32 + lane] + sB[lane]);
    float accv = 0.f;
#pragma unroll
    for (int k = 0; k < 32; k++) {
        float a = __shfl_sync(0xffffffffu, r, k);
        if (lane < 16) accv += a * sW[k * 16 + lane];
    }
    if (lane < 16) {
        float di = dinv[n];
        xw[(size_t)n * 16 + lane] = accv;
        outbuf[(size_t)n * 16 + lane] = accv * di * di;
    }
}

__global__ void gcn_scatter16_kernel(const int* __restrict__ src,
                                     const int* __restrict__ dst,
                                     const float* __restrict__ dinv,
                                     const float* __restrict__ xw,
                                     float* __restrict__ outbuf, int E) {
    int idx = blockIdx.x * blockDim.x + threadIdx.x;
    int e = idx >> 2, q = idx & 3;
    if (e >= E) return;
    int s = src[e], d = dst[e];
    float w = dinv[s] * dinv[d];
    float4 v = *(const float4*)&xw[(size_t)s * 16 + q * 4];
    v.x *= w; v.y *= w; v.z *= w; v.w *= w;
    float* p = &outbuf[(size_t)d * 16 + q * 4];
    asm volatile("red.global.add.v4.f32 [%0], {%1,%2,%3,%4};"
                 :: "l"(p), "f"(v.x), "f"(v.y), "f"(v.z), "f"(v.w) : "memory");
}

// ---------------- edge head -----------------------------------------------------
__global__ __launch_bounds__(256) void edge_head_kernel(
    const int* __restrict__ ei, const int* __restrict__ mask,
    const float* __restrict__ z, const float* __restrict__ c2b,
    const float* __restrict__ lw1, const float* __restrict__ lb1,
    const float* __restrict__ lw2, const float* __restrict__ lb2,
    float* __restrict__ out, int nsel, int E) {
    __shared__ float sW1[32 * 16], sB1[16], sW2[16 * 2], sB2[2], sCB[16];
    int tid = threadIdx.x;
    for (int i = tid; i < 512; i += 256) sW1[i] = lw1[i];
    if (tid < 16) { sB1[tid] = lb1[tid]; sCB[tid] = c2b[tid]; }
    if (tid < 32) sW2[tid] = lw2[tid];
    if (tid < 2)  sB2[tid] = lb2[tid];
    __syncthreads();
    int j = blockIdx.x * 256 + tid;
    if (j >= nsel) return;
    int idx = mask[j];
    int s = ei[idx], d = ei[E + idx];
    float e[32];
    const float4* zs = (const float4*)&z[(size_t)s * 16];
    const float4* zd = (const float4*)&z[(size_t)d * 16];
#pragma unroll
    for (int k = 0; k < 4; k++) {
        float4 v = zs[k];
        e[4 * k + 0] = v.x + sCB[4 * k + 0];
        e[4 * k + 1] = v.y + sCB[4 * k + 1];
        e[4 * k + 2] = v.z + sCB[4 * k + 2];
        e[4 * k + 3] = v.w + sCB[4 * k + 3];
    }
#pragma unroll
    for (int k = 0; k < 4; k++) {
        float4 v = zd[k];
        e[16 + 4 * k + 0] = v.x + sCB[4 * k + 0];
        e[16 + 4 * k + 1] = v.y + sCB[4 * k + 1];
        e[16 + 4 * k + 2] = v.z + sCB[4 * k + 2];
        e[16 + 4 * k + 3] = v.w + sCB[4 * k + 3];
    }
    float a1[16];
#pragma unroll
    for (int q = 0; q < 16; q++) {
        float accv = sB1[q];
#pragma unroll
        for (int k = 0; k < 32; k++) accv += e[k] * sW1[k * 16 + q];
        a1[q] = elu1(accv);
    }
    float o0 = sB2[0], o1 = sB2[1];
#pragma unroll
    for (int q = 0; q < 16; q++) {
        o0 += a1[q] * sW2[q * 2 + 0];
        o1 += a1[q] * sW2[q * 2 + 1];
    }
    *(float2*)&out[(size_t)j * 2] = make_float2(o0, o1);
}

// ---------------- launch --------------------------------------------------------
extern "C" void kernel_launch(void* const* d_in, const int* in_sizes, int n_in,
                              void* d_out, int out_size) {
    const float* x    = (const float*)d_in[0];
    const int*   ei   = (const int*)d_in[1];
    const int*   mask = (const int*)d_in[2];
    const float* ln_g = (const float*)d_in[3];
    const float* ln_b = (const float*)d_in[4];
    const float* w0   = (const float*)d_in[5];
    const float* b0   = (const float*)d_in[6];
    const float* w1   = (const float*)d_in[7];
    const float* b1   = (const float*)d_in[8];
    const float* w2   = (const float*)d_in[9];
    const float* b2   = (const float*)d_in[10];
    const float* c1w  = (const float*)d_in[11];
    const float* c1b  = (const float*)d_in[12];
    const float* c2w  = (const float*)d_in[13];
    const float* c2b  = (const float*)d_in[14];
    const float* lw1  = (const float*)d_in[15];
    const float* lb1  = (const float*)d_in[16];
    const float* lw2  = (const float*)d_in[17];
    const float* lb2  = (const float*)d_in[18];

    int E    = in_sizes[1] / 2;
    int nsel = in_sizes[2];

    float *h, *h0, *h1, *xw1, *ac1, *xw2, *ac2, *dinv;
    cudaGetSymbolAddress((void**)&h,   g_h);
    cudaGetSymbolAddress((void**)&h0,  g_h0);
    cudaGetSymbolAddress((void**)&h1,  g_h1);
    cudaGetSymbolAddress((void**)&xw1, g_xw1);
    cudaGetSymbolAddress((void**)&ac1, g_ac1);
    cudaGetSymbolAddress((void**)&xw2, g_xw2);
    cudaGetSymbolAddress((void**)&ac2, g_ac2);
    cudaGetSymbolAddress((void**)&dinv, g_dinv);

    static int smem_set = 0;
    if (!smem_set) {
        cudaFuncSetAttribute(tf32_gemm_pipe,
                             cudaFuncAttributeMaxDynamicSharedMemorySize,
                             GEMM_SMEM_BYTES);
        smem_set = 1;
    }

    const int T = 256;

    // ---- degree chain, forked onto side stream to overlap pool+MLP phase ----
    if (g_ss.ok) {
        cudaEventRecord(g_ss.evFork, 0);
        cudaStreamWaitEvent(g_ss.s, g_ss.evFork, 0);
        deg_init_kernel<<<(N_NODES + T - 1) / T, T, 0, g_ss.s>>>(dinv);
        deg_accum_kernel<<<(E + T - 1) / T, T, 0, g_ss.s>>>(ei + E, dinv, E);
        deg_final_kernel<<<(N_NODES + T - 1) / T, T, 0, g_ss.s>>>(dinv);
        cudaEventRecord(g_ss.evJoin, g_ss.s);
    } else {
        deg_init_kernel<<<(N_NODES + T - 1) / T, T>>>(dinv);
        deg_accum_kernel<<<(E + T - 1) / T, T>>>(ei + E, dinv, E);
        deg_final_kernel<<<(N_NODES + T - 1) / T, T>>>(dinv);
    }

    // maxpool + layernorm
    pool_ln_kernel<<<N_NODES, 256>>>(x, ln_g, ln_b, h);

    // MLP stack: big two layers on pipelined tf32 tensor cores
    {
        dim3 grid(512 / 128, (N_NODES + 127) / 128);
        tf32_gemm_pipe<<<grid, 256, GEMM_SMEM_BYTES>>>(h, w0, b0, h0, N_NODES, 512, 1024, 1);
    }
    {
        dim3 grid(128 / 128, (N_NODES + 127) / 128);
        tf32_gemm_pipe<<<grid, 256, GEMM_SMEM_BYTES>>>(h0, w1, b1, h1, N_NODES, 128, 512, 1);
    }

    // join degree chain before anything that reads dinv
    if (g_ss.ok) cudaStreamWaitEvent(0, g_ss.evJoin, 0);

    // fused MLP layer 3 (128->64, fp32) + GCN1 xw (64->32) + self-loop init
    mlp3_gcn1_kernel<<<(N_NODES + 127) / 128, 256>>>(h1, w2, b2, c1w, dinv,
                                                     xw1, ac1, N_NODES);
    {
        long long tot = (long long)E * 8;
        gcn_scatter32_kernel<<<(int)((tot + T - 1) / T), T>>>(ei, ei + E, dinv, xw1, ac1, E);
    }

    // GCN conv 2 (32->16), bias+ELU of conv1 fused into the load
    gcn_xw2_kernel<<<(N_NODES + 7) / 8, 256>>>(ac1, c1b, c2w, dinv, xw2, ac2);
    {
        long long tot = (long long)E * 4;
        gcn_scatter16_kernel<<<(int)((tot + T - 1) / T), T>>>(ei, ei + E, dinv, xw2, ac2, E);
    }

    // edge head
    edge_head_kernel<<<(nsel + 255) / 256, 256>>>(ei, mask, ac2, c2b, lw1, lb1, lw2,
                                                  lb2, (float*)d_out, nsel, E);
}

// round 10
// speedup vs baseline: 2.5565x; 1.0078x over previous
#include <cuda_runtime.h>
#include <cuda_bf16.h>
#include <math.h>
#include <stdint.h>

#define N_NODES 50000
#define F_IN    2048
#define POOLD   1024

// ---------------- scratch (static device globals; no allocations) -------------
__device__ float g_h  [(size_t)N_NODES * 1024];  // pooled+LN (tf32-rounded)
__device__ float g_h0 [(size_t)N_NODES * 512];   // (tf32-rounded)
__device__ float g_h1 [(size_t)N_NODES * 128];
__device__ float g_xw1[(size_t)N_NODES * 32];
__device__ float g_ac1[(size_t)N_NODES * 32];    // gcn1 accumulator (raw, pre-act)
__device__ float g_xw2[(size_t)N_NODES * 16];
__device__ float g_ac2[(size_t)N_NODES * 16];    // gcn2 accumulator (z before bias)
__device__ float g_dinv[N_NODES];                 // deg -> rsqrt(deg)
__device__ float g_w0r[(size_t)1024 * 512];       // w0, tf32-rounded [K][N]
__device__ float g_w1r[(size_t)512 * 128];        // w1, tf32-rounded [K][N]

__device__ __forceinline__ float elu1(float v) { return v > 0.f ? v : expm1f(v); }

__device__ __forceinline__ unsigned f2tf32(float v) {
    unsigned r;
    asm("cvt.rna.tf32.f32 %0, %1;" : "=r"(r) : "f"(v));
    return r;
}

// ---------------- side-stream (created in static ctor, outside capture) --------
struct SideStream {
    cudaStream_t s = nullptr;
    cudaEvent_t evFork = nullptr, evJoin = nullptr;
    bool ok = false;
    SideStream() {
        if (cudaStreamCreateWithFlags(&s, cudaStreamNonBlocking) == cudaSuccess &&
            cudaEventCreateWithFlags(&evFork, cudaEventDisableTiming) == cudaSuccess &&
            cudaEventCreateWithFlags(&evJoin, cudaEventDisableTiming) == cudaSuccess)
            ok = true;
    }
};
static SideStream g_ss;

// ---------------- degree ------------------------------------------------------
__global__ void deg_init_kernel(float* deg) {
    int i = blockIdx.x * blockDim.x + threadIdx.x;
    if (i < N_NODES) deg[i] = 1.0f;
}
__global__ void deg_accum_kernel(const int* __restrict__ dst, float* deg, int E) {
    int e = blockIdx.x * blockDim.x + threadIdx.x;
    if (e < E) atomicAdd(&deg[dst[e]], 1.0f);
}
__global__ void deg_final_kernel(float* deg) {
    int i = blockIdx.x * blockDim.x + threadIdx.x;
    if (i < N_NODES) deg[i] = rsqrtf(deg[i]);
}

// ---------------- weight prep: tf32 round (layout unchanged) -------------------
__global__ void prep_round_kernel(const float* __restrict__ w,
                                  float* __restrict__ wr, int total) {
    int i = blockIdx.x * blockDim.x + threadIdx.x;
    if (i < total) wr[i] = __uint_as_float(f2tf32(w[i]));
}

// ---------------- maxpool(2) + layernorm (tf32-rounded output) -----------------
__global__ void pool_ln_kernel(const float* __restrict__ x,
                               const float* __restrict__ g,
                               const float* __restrict__ b,
                               float* __restrict__ h) {
    int n = blockIdx.x;
    int t = threadIdx.x;  // 256
    const float4* xr = (const float4*)(x + (size_t)n * F_IN);
    float m[2][2];
    float sum = 0.f, sumsq = 0.f;
#pragma unroll
    for (int jj = 0; jj < 2; jj++) {
        int j = jj * 256 + t;
        float4 v = xr[j];
        float m0 = fmaxf(v.x, v.y);
        float m1 = fmaxf(v.z, v.w);
        m[jj][0] = m0; m[jj][1] = m1;
        sum += m0 + m1;
        sumsq += m0 * m0 + m1 * m1;
    }
    __shared__ float ssum[8], ssq[8];
#pragma unroll
    for (int off = 16; off > 0; off >>= 1) {
        sum   += __shfl_down_sync(0xffffffffu, sum, off);
        sumsq += __shfl_down_sync(0xffffffffu, sumsq, off);
    }
    int w = t >> 5, l = t & 31;
    if (l == 0) { ssum[w] = sum; ssq[w] = sumsq; }
    __syncthreads();
    __shared__ float s_mu, s_rstd;
    if (t == 0) {
        float S = 0.f, Q = 0.f;
#pragma unroll
        for (int i = 0; i < 8; i++) { S += ssum[i]; Q += ssq[i]; }
        float mu = S * (1.0f / POOLD);
        float var = Q * (1.0f / POOLD) - mu * mu;
        s_mu = mu;
        s_rstd = rsqrtf(var + 1e-5f);
    }
    __syncthreads();
    float mu = s_mu, rstd = s_rstd;
    float* hr = h + (size_t)n * POOLD;
#pragma unroll
    for (int jj = 0; jj < 2; jj++) {
        int j = jj * 256 + t;
        float o0 = (m[jj][0] - mu) * rstd * g[2 * j] + b[2 * j];
        float o1 = (m[jj][1] - mu) * rstd * g[2 * j + 1] + b[2 * j + 1];
        o0 = __uint_as_float(f2tf32(o0));
        o1 = __uint_as_float(f2tf32(o1));
        *(float2*)&hr[2 * j] = make_float2(o0, o1);
    }
}

// ---------------- 3-stage pipelined tf32 tensor GEMM ---------------------------
// C = act(A @ B + bias); A and B are PRE-ROUNDED to tf32 -> raw-bit fragment loads.
// Block tile 128x128x32, 256 threads = 8 warps (2M x 4N), warp tile 64x32.
#define ASTG (128 * 36)
#define BSTG (32 * 136)
#define NSTAGE 3
#define GEMM_SMEM_BYTES (NSTAGE * (ASTG + BSTG) * 4)

__device__ __forceinline__ void cp16(uint32_t sdst, const float* gsrc, int pred_bytes) {
    asm volatile("cp.async.cg.shared.global [%0], [%1], 16, %2;"
                 :: "r"(sdst), "l"(gsrc), "r"(pred_bytes));
}

__global__ __launch_bounds__(256, 2) void tf32_gemm_pipe(
    const float* __restrict__ A, const float* __restrict__ B,
    const float* __restrict__ bias, float* __restrict__ C,
    int M, int N, int K, int do_elu, int do_round) {
    extern __shared__ float smem[];
    float* AsBase = smem;                     // NSTAGE x [128][36]
    float* BsBase = smem + NSTAGE * ASTG;     // NSTAGE x [32][136]

    int tid = threadIdx.x;
    int warp = tid >> 5, lane = tid & 31;
    int lg = lane >> 2, lq = lane & 3;
    int warpM = warp & 1, warpN = warp >> 1;
    int Rw = warpM * 64, Cw = warpN * 32;
    int rowBase = blockIdx.y * 128;       // y = row tile (slow)
    int colBase = blockIdx.x * 128;       // x = col tile (fast -> L2 reuse of A)

    float acc[4][4][4];
#pragma unroll
    for (int mt = 0; mt < 4; mt++)
#pragma unroll
        for (int nt = 0; nt < 4; nt++)
#pragma unroll
            for (int r = 0; r < 4; r++) acc[mt][nt][r] = 0.f;

    int iters = K >> 5;

    uint32_t sA = (uint32_t)__cvta_generic_to_shared(AsBase);
    uint32_t sB = (uint32_t)__cvta_generic_to_shared(BsBase);

#define LOAD_STAGE(IT)                                                          \
    do {                                                                        \
        int k0 = (IT) * 32;                                                     \
        int buf = (IT) % NSTAGE;                                                \
        uint32_t aBuf = sA + buf * (ASTG * 4);                                  \
        uint32_t bBuf = sB + buf * (BSTG * 4);                                  \
        _Pragma("unroll")                                                       \
        for (int i = 0; i < 4; i++) {                                           \
            int idx = i * 256 + tid;          /* [0,1024) */                    \
            int row = idx >> 3, ch = idx & 7;                                   \
            int grow = rowBase + row;                                           \
            const float* src = A + (size_t)grow * K + k0 + ch * 4;              \
            cp16(aBuf + (row * 36 + ch * 4) * 4, src, grow < M ? 16 : 0);       \
        }                                                                       \
        _Pragma("unroll")                                                       \
        for (int i = 0; i < 4; i++) {                                           \
            int idx = i * 256 + tid;          /* [0,1024) */                    \
            int row = idx >> 5, ch = idx & 31;                                  \
            const float* src = B + (size_t)(k0 + row) * N + colBase + ch * 4;   \
            cp16(bBuf + (row * 136 + ch * 4) * 4, src, 16);                     \
        }                                                                       \
        asm volatile("cp.async.commit_group;");                                 \
    } while (0)

    LOAD_STAGE(0);
    if (iters > 1) LOAD_STAGE(1);

    for (int it = 0; it < iters; it++) {
        if (it + 2 < iters) {
            LOAD_STAGE(it + 2);
            asm volatile("cp.async.wait_group 2;");
        } else if (it + 1 < iters) {
            asm volatile("cp.async.wait_group 1;");
        } else {
            asm volatile("cp.async.wait_group 0;");
        }
        __syncthreads();

        const float* Asb = AsBase + (it % NSTAGE) * ASTG;
        const float* Bsb = BsBase + (it % NSTAGE) * BSTG;
#pragma unroll
        for (int kk = 0; kk < 32; kk += 8) {
            unsigned a[4][4], bfr[4][2];
#pragma unroll
            for (int mt = 0; mt < 4; mt++) {
                int r0 = Rw + mt * 16 + lg;
                a[mt][0] = __float_as_uint(Asb[r0 * 36 + kk + lq]);
                a[mt][1] = __float_as_uint(Asb[(r0 + 8) * 36 + kk + lq]);
                a[mt][2] = __float_as_uint(Asb[r0 * 36 + kk + lq + 4]);
                a[mt][3] = __float_as_uint(Asb[(r0 + 8) * 36 + kk + lq + 4]);
            }
#pragma unroll
            for (int nt = 0; nt < 4; nt++) {
                int c0 = Cw + nt * 8 + lg;
                bfr[nt][0] = __float_as_uint(Bsb[(kk + lq) * 136 + c0]);
                bfr[nt][1] = __float_as_uint(Bsb[(kk + lq + 4) * 136 + c0]);
            }
#pragma unroll
            for (int mt = 0; mt < 4; mt++)
#pragma unroll
                for (int nt = 0; nt < 4; nt++) {
                    asm volatile(
                        "mma.sync.aligned.m16n8k8.row.col.f32.tf32.tf32.f32 "
                        "{%0,%1,%2,%3}, {%4,%5,%6,%7}, {%8,%9}, {%0,%1,%2,%3};"
                        : "+f"(acc[mt][nt][0]), "+f"(acc[mt][nt][1]),
                          "+f"(acc[mt][nt][2]), "+f"(acc[mt][nt][3])
                        : "r"(a[mt][0]), "r"(a[mt][1]), "r"(a[mt][2]), "r"(a[mt][3]),
                          "r"(bfr[nt][0]), "r"(bfr[nt][1]));
                }
        }
        __syncthreads();
    }
#undef LOAD_STAGE

    // ---- epilogue: bias + optional ELU (+ tf32 round for next tf32 layer) ----
#pragma unroll
    for (int mt = 0; mt < 4; mt++) {
#pragma unroll
        for (int nt = 0; nt < 4; nt++) {
            int col = colBase + Cw + nt * 8 + lq * 2;
            float b0 = bias[col], b1 = bias[col + 1];
            int r0 = rowBase + Rw + mt * 16 + lg;
            if (r0 < M) {
                float v0 = acc[mt][nt][0] + b0;
                float v1 = acc[mt][nt][1] + b1;
                if (do_elu) { v0 = elu1(v0); v1 = elu1(v1); }
                if (do_round) {
                    v0 = __uint_as_float(f2tf32(v0));
                    v1 = __uint_as_float(f2tf32(v1));
                }
                *(float2*)&C[(size_t)r0 * N + col] = make_float2(v0, v1);
            }
            int r1 = r0 + 8;
            if (r1 < M) {
                float v2 = acc[mt][nt][2] + b0;
                float v3 = acc[mt][nt][3] + b1;
                if (do_elu) { v2 = elu1(v2); v3 = elu1(v3); }
                if (do_round) {
                    v2 = __uint_as_float(f2tf32(v2));
                    v3 = __uint_as_float(f2tf32(v3));
                }
                *(float2*)&C[(size_t)r1 * N + col] = make_float2(v2, v3);
            }
        }
    }
}

// ---------------- fused: h2 = elu(h1 @ w2 + b2); xw1 = h2 @ c1w; self-loop init --
__global__ __launch_bounds__(256) void mlp3_gcn1_kernel(
    const float* __restrict__ h1,   // [M,128]
    const float* __restrict__ w2,   // [128,64]
    const float* __restrict__ b2,   // [64]
    const float* __restrict__ c1w,  // [64,32]
    const float* __restrict__ dinv,
    float* __restrict__ xw, float* __restrict__ outbuf, int M) {
    __shared__ float sbuf[128 * 68];
    __shared__ float sW[64 * 32];
    __shared__ float sB2[64];

    int tid = threadIdx.x;
    for (int i = tid; i < 64 * 32; i += 256) sW[i] = c1w[i];
    if (tid < 64) sB2[tid] = b2[tid];

    float* As = sbuf;                  // [16][132]
    float* Bs = sbuf + 16 * 132;       // [16][64]

    int tx = tid & 15, ty = tid >> 4;
    int rowBase = blockIdx.x * 128;

    float acc[8][4];
#pragma unroll
    for (int i = 0; i < 8; i++)
#pragma unroll
        for (int j = 0; j < 4; j++) acc[i][j] = 0.f;

    int ar = tid >> 2;
    int ac = (tid & 3) * 4;
    int br = tid >> 4;
    int bc = (tid & 15) * 4;

    for (int k0 = 0; k0 < 128; k0 += 16) {
#pragma unroll
        for (int gidx = 0; gidx < 2; gidx++) {
            int r = ar + gidx * 64;
            int grow = rowBase + r;
            float4 v = make_float4(0.f, 0.f, 0.f, 0.f);
            if (grow < M) v = *(const float4*)&h1[(size_t)grow * 128 + k0 + ac];
            As[(ac + 0) * 132 + r] = v.x; As[(ac + 1) * 132 + r] = v.y;
            As[(ac + 2) * 132 + r] = v.z; As[(ac + 3) * 132 + r] = v.w;
        }
        {
            float4 v = *(const float4*)&w2[(size_t)(k0 + br) * 64 + bc];
            Bs[br * 64 + bc + 0] = v.x; Bs[br * 64 + bc + 1] = v.y;
            Bs[br * 64 + bc + 2] = v.z; Bs[br * 64 + bc + 3] = v.w;
        }
        __syncthreads();
#pragma unroll
        for (int k = 0; k < 16; k++) {
            float ra[8], rb[4];
#pragma unroll
            for (int i = 0; i < 8; i++) ra[i] = As[k * 132 + ty * 8 + i];
#pragma unroll
            for (int j = 0; j < 4; j++) rb[j] = Bs[k * 64 + tx * 4 + j];
#pragma unroll
            for (int i = 0; i < 8; i++)
#pragma unroll
                for (int j = 0; j < 4; j++) acc[i][j] += ra[i] * rb[j];
        }
        __syncthreads();
    }

#pragma unroll
    for (int i = 0; i < 8; i++) {
        int row = ty * 8 + i;
#pragma unroll
        for (int j = 0; j < 4; j++) {
            int col = tx * 4 + j;
            sbuf[row * 68 + col] = elu1(acc[i][j] + sB2[col]);
        }
    }
    __syncthreads();

    int warp = tid >> 5, lane = tid & 31;
#pragma unroll 1
    for (int r = 0; r < 16; r++) {
        int row = warp + r * 8;
        int n = rowBase + row;
        if (n >= M) continue;
        float r0 = sbuf[row * 68 + lane], r1 = sbuf[row * 68 + 32 + lane];
        float accv = 0.f;
#pragma unroll
        for (int k = 0; k < 32; k++) {
            float a = __shfl_sync(0xffffffffu, r0, k);
            accv += a * sW[k * 32 + lane];
        }
#pragma unroll
        for (int k = 0; k < 32; k++) {
            float a = __shfl_sync(0xffffffffu, r1, k);
            accv += a * sW[(k + 32) * 32 + lane];
        }
        float di = dinv[n];
        xw[(size_t)n * 32 + lane] = accv;
        outbuf[(size_t)n * 32 + lane] = accv * di * di;
    }
}

// scatter: out[dst] += xw[src]*dinv[src]*dinv[dst], 8 lanes/edge, red.v4
__global__ void gcn_scatter32_kernel(const int* __restrict__ src,
                                     const int* __restrict__ dst,
                                     const float* __restrict__ dinv,
                                     const float* __restrict__ xw,
                                     float* __restrict__ outbuf, int E) {
    int idx = blockIdx.x * blockDim.x + threadIdx.x;
    int e = idx >> 3, q = idx & 7;
    if (e >= E) return;
    int s = src[e], d = dst[e];
    float w = dinv[s] * dinv[d];
    float4 v = *(const float4*)&xw[(size_t)s * 32 + q * 4];
    v.x *= w; v.y *= w; v.z *= w; v.w *= w;
    float* p = &outbuf[(size_t)d * 32 + q * 4];
    asm volatile("red.global.add.v4.f32 [%0], {%1,%2,%3,%4};"
                 :: "l"(p), "f"(v.x), "f"(v.y), "f"(v.z), "f"(v.w) : "memory");
}

// ---------------- GCN2: xw2 = elu(ac1 + c1b) @ c2w (32->16), fused activation ----
__global__ __launch_bounds__(256) void gcn_xw2_kernel(
    const float* __restrict__ g1raw, const float* __restrict__ c1b,
    const float* __restrict__ W,  // 32x16
    const float* __restrict__ dinv,
    float* __restrict__ xw, float* __restrict__ outbuf) {
    __shared__ float sW[32 * 16];
    __shared__ float sB[32];
    int tid = threadIdx.x;
    for (int i = tid; i < 32 * 16; i += 256) sW[i] = W[i];
    if (tid < 32) sB[tid] = c1b[tid];
    __syncthreads();
    int warp = tid >> 5, lane = tid & 31;
    int n = blockIdx.x * 8 + warp;
    if (n >= N_NODES) return;
    float r = elu1(g1raw[(size_t)n * 32 + lane] + sB[lane]);
    float accv = 0.f;
#pragma unroll
    for (int k = 0; k < 32; k++) {
        float a = __shfl_sync(0xffffffffu, r, k);
        if (lane < 16) accv += a * sW[k * 16 + lane];
    }
    if (lane < 16) {
        float di = dinv[n];
        xw[(size_t)n * 16 + lane] = accv;
        outbuf[(size_t)n * 16 + lane] = accv * di * di;
    }
}

__global__ void gcn_scatter16_kernel(const int* __restrict__ src,
                                     const int* __restrict__ dst,
                                     const float* __restrict__ dinv,
                                     const float* __restrict__ xw,
                                     float* __restrict__ outbuf, int E) {
    int idx = blockIdx.x * blockDim.x + threadIdx.x;
    int e = idx >> 2, q = idx & 3;
    if (e >= E) return;
    int s = src[e], d = dst[e];
    float w = dinv[s] * dinv[d];
    float4 v = *(const float4*)&xw[(size_t)s * 16 + q * 4];
    v.x *= w; v.y *= w; v.z *= w; v.w *= w;
    float* p = &outbuf[(size_t)d * 16 + q * 4];
    asm volatile("red.global.add.v4.f32 [%0], {%1,%2,%3,%4};"
                 :: "l"(p), "f"(v.x), "f"(v.y), "f"(v.z), "f"(v.w) : "memory");
}

// ---------------- edge head -----------------------------------------------------
__global__ __launch_bounds__(256) void edge_head_kernel(
    const int* __restrict__ ei, const int* __restrict__ mask,
    const float* __restrict__ z, const float* __restrict__ c2b,
    const float* __restrict__ lw1, const float* __restrict__ lb1,
    const float* __restrict__ lw2, const float* __restrict__ lb2,
    float* __restrict__ out, int nsel, int E) {
    __shared__ float sW1[32 * 16], sB1[16], sW2[16 * 2], sB2[2], sCB[16];
    int tid = threadIdx.x;
    for (int i = tid; i < 512; i += 256) sW1[i] = lw1[i];
    if (tid < 16) { sB1[tid] = lb1[tid]; sCB[tid] = c2b[tid]; }
    if (tid < 32) sW2[tid] = lw2[tid];
    if (tid < 2)  sB2[tid] = lb2[tid];
    __syncthreads();
    int j = blockIdx.x * 256 + tid;
    if (j >= nsel) return;
    int idx = mask[j];
    int s = ei[idx], d = ei[E + idx];
    float e[32];
    const float4* zs = (const float4*)&z[(size_t)s * 16];
    const float4* zd = (const float4*)&z[(size_t)d * 16];
#pragma unroll
    for (int k = 0; k < 4; k++) {
        float4 v = zs[k];
        e[4 * k + 0] = v.x + sCB[4 * k + 0];
        e[4 * k + 1] = v.y + sCB[4 * k + 1];
        e[4 * k + 2] = v.z + sCB[4 * k + 2];
        e[4 * k + 3] = v.w + sCB[4 * k + 3];
    }
#pragma unroll
    for (int k = 0; k < 4; k++) {
        float4 v = zd[k];
        e[16 + 4 * k + 0] = v.x + sCB[4 * k + 0];
        e[16 + 4 * k + 1] = v.y + sCB[4 * k + 1];
        e[16 + 4 * k + 2] = v.z + sCB[4 * k + 2];
        e[16 + 4 * k + 3] = v.w + sCB[4 * k + 3];
    }
    float a1[16];
#pragma unroll
    for (int q = 0; q < 16; q++) {
        float accv = sB1[q];
#pragma unroll
        for (int k = 0; k < 32; k++) accv += e[k] * sW1[k * 16 + q];
        a1[q] = elu1(accv);
    }
    float o0 = sB2[0], o1 = sB2[1];
#pragma unroll
    for (int q = 0; q < 16; q++) {
        o0 += a1[q] * sW2[q * 2 + 0];
        o1 += a1[q] * sW2[q * 2 + 1];
    }
    *(float2*)&out[(size_t)j * 2] = make_float2(o0, o1);
}

// ---------------- launch --------------------------------------------------------
extern "C" void kernel_launch(void* const* d_in, const int* in_sizes, int n_in,
                              void* d_out, int out_size) {
    const float* x    = (const float*)d_in[0];
    const int*   ei   = (const int*)d_in[1];
    const int*   mask = (const int*)d_in[2];
    const float* ln_g = (const float*)d_in[3];
    const float* ln_b = (const float*)d_in[4];
    const float* w0   = (const float*)d_in[5];
    const float* b0   = (const float*)d_in[6];
    const float* w1   = (const float*)d_in[7];
    const float* b1   = (const float*)d_in[8];
    const float* w2   = (const float*)d_in[9];
    const float* b2   = (const float*)d_in[10];
    const float* c1w  = (const float*)d_in[11];
    const float* c1b  = (const float*)d_in[12];
    const float* c2w  = (const float*)d_in[13];
    const float* c2b  = (const float*)d_in[14];
    const float* lw1  = (const float*)d_in[15];
    const float* lb1  = (const float*)d_in[16];
    const float* lw2  = (const float*)d_in[17];
    const float* lb2  = (const float*)d_in[18];

    int E    = in_sizes[1] / 2;
    int nsel = in_sizes[2];

    float *h, *h0, *h1, *xw1, *ac1, *xw2, *ac2, *dinv, *w0r, *w1r;
    cudaGetSymbolAddress((void**)&h,   g_h);
    cudaGetSymbolAddress((void**)&h0,  g_h0);
    cudaGetSymbolAddress((void**)&h1,  g_h1);
    cudaGetSymbolAddress((void**)&xw1, g_xw1);
    cudaGetSymbolAddress((void**)&ac1, g_ac1);
    cudaGetSymbolAddress((void**)&xw2, g_xw2);
    cudaGetSymbolAddress((void**)&ac2, g_ac2);
    cudaGetSymbolAddress((void**)&dinv, g_dinv);
    cudaGetSymbolAddress((void**)&w0r, g_w0r);
    cudaGetSymbolAddress((void**)&w1r, g_w1r);

    static int smem_set = 0;
    if (!smem_set) {
        cudaFuncSetAttribute(tf32_gemm_pipe,
                             cudaFuncAttributeMaxDynamicSharedMemorySize,
                             GEMM_SMEM_BYTES);
        smem_set = 1;
    }

    const int T = 256;

    // ---- degree chain + weight prep on side stream (hidden under pool_ln) ----
    if (g_ss.ok) {
        cudaEventRecord(g_ss.evFork, 0);
        cudaStreamWaitEvent(g_ss.s, g_ss.evFork, 0);
        deg_init_kernel<<<(N_NODES + T - 1) / T, T, 0, g_ss.s>>>(dinv);
        deg_accum_kernel<<<(E + T - 1) / T, T, 0, g_ss.s>>>(ei + E, dinv, E);
        deg_final_kernel<<<(N_NODES + T - 1) / T, T, 0, g_ss.s>>>(dinv);
        prep_round_kernel<<<(1024 * 512 + T - 1) / T, T, 0, g_ss.s>>>(w0, w0r, 1024 * 512);
        prep_round_kernel<<<(512 * 128 + T - 1) / T, T, 0, g_ss.s>>>(w1, w1r, 512 * 128);
        cudaEventRecord(g_ss.evJoin, g_ss.s);
    } else {
        deg_init_kernel<<<(N_NODES + T - 1) / T, T>>>(dinv);
        deg_accum_kernel<<<(E + T - 1) / T, T>>>(ei + E, dinv, E);
        deg_final_kernel<<<(N_NODES + T - 1) / T, T>>>(dinv);
        prep_round_kernel<<<(1024 * 512 + T - 1) / T, T>>>(w0, w0r, 1024 * 512);
        prep_round_kernel<<<(512 * 128 + T - 1) / T, T>>>(w1, w1r, 512 * 128);
    }

    // maxpool + layernorm (tf32-rounded output)
    pool_ln_kernel<<<N_NODES, 256>>>(x, ln_g, ln_b, h);

    // join side work before GEMM1 (needs w0r; dinv also covered)
    if (g_ss.ok) cudaStreamWaitEvent(0, g_ss.evJoin, 0);

    // MLP stack: big two layers on pipelined tf32 tensor cores (pre-rounded ops)
    {
        dim3 grid(512 / 128, (N_NODES + 127) / 128);
        tf32_gemm_pipe<<<grid, 256, GEMM_SMEM_BYTES>>>(h, w0r, b0, h0, N_NODES, 512,
                                                       1024, 1 /*elu*/, 1 /*round*/);
    }
    {
        dim3 grid(128 / 128, (N_NODES + 127) / 128);
        tf32_gemm_pipe<<<grid, 256, GEMM_SMEM_BYTES>>>(h0, w1r, b1, h1, N_NODES, 128,
                                                       512, 1 /*elu*/, 0 /*no round*/);
    }

    // fused MLP layer 3 (128->64, fp32) + GCN1 xw (64->32) + self-loop init
    mlp3_gcn1_kernel<<<(N_NODES + 127) / 128, 256>>>(h1, w2, b2, c1w, dinv,
                                                     xw1, ac1, N_NODES);
    {
        long long tot = (long long)E * 8;
        gcn_scatter32_kernel<<<(int)((tot + T - 1) / T), T>>>(ei, ei + E, dinv, xw1, ac1, E);
    }

    // GCN conv 2 (32->16), bias+ELU of conv1 fused into the load
    gcn_xw2_kernel<<<(N_NODES + 7) / 8, 256>>>(ac1, c1b, c2w, dinv, xw2, ac2);
    {
        long long tot = (long long)E * 4;
        gcn_scatter16_kernel<<<(int)((tot + T - 1) / T), T>>>(ei, ei + E, dinv, xw2, ac2, E);
    }

    // edge head
    edge_head_kernel<<<(nsel + 255) / 256, 256>>>(ei, mask, ac2, c2b, lw1, lb1, lw2,
                                                  lb2, (float*)d_out, nsel, E);
}